// round 10
// baseline (speedup 1.0000x reference)
#include <cuda_runtime.h>
#include <cuda_fp16.h>
#include <cuda_bf16.h>
#include <math_constants.h>
#include <cstdint>

// ---------------- shapes ----------------
#define B_  256
#define T_  250
#define D_  700
#define H_  1024
#define O_  20
#define M_  (B_ * T_)   // 64000
#define KP_ 704         // K padded to multiple of 64

// ---------------- main GEMM tiling ----------------
#define BM 128
#define BN 128
#define BK 32
#define NCHUNK (KP_ / BK)              // 22
#define A_TILE_B (BM * BK * 2)         // 8192 per split
#define W_TILE_B (BN * BK * 2)         // 8192 per split
#define STAGE_B (2 * A_TILE_B + 2 * W_TILE_B)  // 32768
#define NSTAGE 3
#define SMEM_TOTAL (NSTAGE * STAGE_B)  // 98304 -> 2 CTAs/SM

#define A_SCALE 2048.0f
#define W_SCALE 64.0f
#define INV_SCALE (1.0f / (A_SCALE * W_SCALE))   // 2^-17, exact

// ---------------- phase-B (d2) GEMM tiling ----------------
#define PB_ROWS 256
#define PB_K    1024
#define PB_BK   64
#define PB_NCH  (PB_K / PB_BK)             // 16
#define PB_SPKBUF  (PB_ROWS * PB_BK * 2)   // 32768 per buffer
#define PB_W2TILE  (32 * PB_BK * 2)        // 4096 per split
#define PB_W2STAGE (2 * PB_W2TILE)         // 8192
#define PB_W2RING  4
#define PB_SMEM (2 * PB_SPKBUF + PB_W2RING * PB_W2STAGE)   // 98304

// ---------------- scratch (static device globals; no allocation) ----------------
__device__ float g_d1[(size_t)M_ * H_];
__device__ __half g_Ah[(size_t)M_ * KP_];
__device__ __half g_Al[(size_t)M_ * KP_];
__device__ __half g_Wh[(size_t)H_ * KP_];
__device__ __half g_Wl[(size_t)H_ * KP_];
__device__ uint32_t g_msk[(size_t)M_ * 32];            // spike bitmasks
__device__ __nv_bfloat16 g_W2s[2][32 * PB_K];          // W2 hi/lo bf16 splits (bit-permuted)
__device__ float g_d2[(size_t)M_ * 32];                // d2 (padded to 32 outputs)

// ---------------- family-safe PTX helpers ----------------
__device__ __forceinline__ uint32_t smem_to_u32(const void* smem_ptr) {
    uint32_t addr;
    asm("{ .reg .u64 tmp; cvta.to.shared.u64 tmp, %1; cvt.u32.u64 %0, tmp; }"
        : "=r"(addr) : "l"(smem_ptr));
    return addr;
}
#define CP_ASYNC16(dst_u32, src_ptr) \
    asm volatile("cp.async.cg.shared.global [%0], [%1], 16;" \
        :: "r"(dst_u32), "l"(src_ptr))
#define CP_COMMIT() asm volatile("cp.async.commit_group;" ::: "memory")
#define CP_WAIT2()  asm volatile("cp.async.wait_group 2;" ::: "memory")

__device__ __forceinline__ void ldsm_x4(uint32_t& r0, uint32_t& r1,
                                        uint32_t& r2, uint32_t& r3, uint32_t addr) {
    asm volatile("ldmatrix.sync.aligned.m8n8.x4.shared.b16 {%0,%1,%2,%3}, [%4];"
        : "=r"(r0), "=r"(r1), "=r"(r2), "=r"(r3) : "r"(addr));
}
__device__ __forceinline__ void mma16816_f16(float* c, const uint32_t* a, const uint32_t* b) {
    asm volatile(
        "mma.sync.aligned.m16n8k16.row.col.f32.f16.f16.f32 "
        "{%0,%1,%2,%3}, {%4,%5,%6,%7}, {%8,%9}, {%0,%1,%2,%3};"
        : "+f"(c[0]), "+f"(c[1]), "+f"(c[2]), "+f"(c[3])
        : "r"(a[0]), "r"(a[1]), "r"(a[2]), "r"(a[3]), "r"(b[0]), "r"(b[1]));
}
__device__ __forceinline__ void mma16816_bf16(float* c, const uint32_t* a, const uint32_t* b) {
    asm volatile(
        "mma.sync.aligned.m16n8k16.row.col.f32.bf16.bf16.f32 "
        "{%0,%1,%2,%3}, {%4,%5,%6,%7}, {%8,%9}, {%0,%1,%2,%3};"
        : "+f"(c[0]), "+f"(c[1]), "+f"(c[2]), "+f"(c[3])
        : "r"(a[0]), "r"(a[1]), "r"(a[2]), "r"(a[3]), "r"(b[0]), "r"(b[1]));
}
#define SWZ128(o) ((o) ^ (((o) >> 3) & 0x70))
// pair-packed address for 64-byte-row tiles (2 rows share a 128B line) [R8-validated]
#define PK64(row, colbyte) ((uint32_t)((((row) >> 1) * 128) + (((row) & 1) * 64) + (colbyte)))

// expand 2 spike bits into packed bf16x2 (1.0f / 0.0f halves)
__device__ __forceinline__ uint32_t expand2(uint32_t b) {
    return ((b & 1u) * 0x3F80u) | ((b >> 1) * 0x3F800000u);
}

// ---------------------------------------------------------------------------
// Kernel 0: fp32 -> 2x fp16 split with pre-scale, 8 elems/thread.
// ---------------------------------------------------------------------------
__global__ void split2_kernel(const float* __restrict__ src, int rows, float scale,
                              __half* __restrict__ o0, __half* __restrict__ o1)
{
    const int GPR = KP_ / 8;  // 88
    long long idx = (long long)blockIdx.x * blockDim.x + threadIdx.x;
    if (idx >= (long long)rows * GPR) return;
    int m = (int)(idx / GPR);
    int g = (int)(idx % GPR);
    const float* sp = src + (size_t)m * D_ + g * 8;
    float4 f0 = *(const float4*)sp;                         // g*8 <= 696 < 700 always
    float4 f1 = (g < GPR - 1) ? *(const float4*)(sp + 4)
                              : make_float4(0.f, 0.f, 0.f, 0.f);
    float a[8] = {f0.x * scale, f0.y * scale, f0.z * scale, f0.w * scale,
                  f1.x * scale, f1.y * scale, f1.z * scale, f1.w * scale};
    unsigned short h0[8], h1[8];
#pragma unroll
    for (int i = 0; i < 8; i++) {
        __half hi = __float2half_rn(a[i]);
        __half lo = __float2half_rn(a[i] - __half2float(hi));
        h0[i] = __half_as_ushort(hi);
        h1[i] = __half_as_ushort(lo);
    }
    size_t off = (size_t)m * KP_ + g * 8;
    *(uint4*)(o0 + off) = make_uint4(
        (uint32_t)h0[1] << 16 | h0[0], (uint32_t)h0[3] << 16 | h0[2],
        (uint32_t)h0[5] << 16 | h0[4], (uint32_t)h0[7] << 16 | h0[6]);
    *(uint4*)(o1 + off) = make_uint4(
        (uint32_t)h1[1] << 16 | h1[0], (uint32_t)h1[3] << 16 | h1[2],
        (uint32_t)h1[5] << 16 | h1[4], (uint32_t)h1[7] << 16 | h1[6]);
}

// ---------------------------------------------------------------------------
// Kernel 0b: W2 -> 2x bf16 splits, PERMUTED to ballot bit order.
// ---------------------------------------------------------------------------
__global__ void split_w2_kernel(const float* __restrict__ W2)
{
    int idx = blockIdx.x * blockDim.x + threadIdx.x;
    if (idx >= 32 * PB_K) return;
    int o = idx / PB_K;
    int p = idx % PB_K;
    int w = p >> 5, l = p & 31;
    int h = (w >> 2) * 128 + l * 4 + (w & 3);
    float v = (o < O_) ? W2[o * H_ + h] : 0.0f;
    __nv_bfloat16 hi = __float2bfloat16(v);
    __nv_bfloat16 lo = __float2bfloat16(v - __bfloat162float(hi));
    g_W2s[0][idx] = hi;
    g_W2s[1][idx] = lo;
}

// ---------------------------------------------------------------------------
// Kernel 1: HMMA fp16 GEMM, fp32 emulation via 3 cross-products.
// BM=128, BN=128, BK=32, NSTAGE=3 (96KB, 2 CTAs/SM).
// 8 warps in 4(m) x 2(n); warp tile 32x64 -> 12 LDSM per 48 MMA per kk.
// Term-ordered fragment loading to keep regs <= 128.
// ---------------------------------------------------------------------------
__global__ __launch_bounds__(256, 2)
void gemm_hmma_kernel(const float* __restrict__ bias)
{
    extern __shared__ __align__(1024) char smem[];
    const uint32_t smem_base = smem_to_u32(smem);
    const int tid  = threadIdx.x;
    const int wid  = tid >> 5;
    const int lane = tid & 31;
    const int wm = wid >> 1;       // 0..3 (m)
    const int wn = wid & 1;        // 0..1 (n)
    const int bm = blockIdx.y * BM;
    const int bn = blockIdx.x * BN;

    // cp.async geometry: each split-tile is 128 rows x 64B = 512 16B-units, 2/thread.
    uint32_t sdst[2];
    size_t   goff[2];
#pragma unroll
    for (int j = 0; j < 2; j++) {
        int u = tid + j * 256;
        int row = u >> 2, cu = u & 3;
        sdst[j] = SWZ128(PK64(row, cu * 16));
        goff[j] = (size_t)row * KP_ + cu * 8;
    }
    const __half* Asrc[2] = { g_Ah + (size_t)bm * KP_, g_Al + (size_t)bm * KP_ };
    const __half* Wsrc[2] = { g_Wh + (size_t)bn * KP_, g_Wl + (size_t)bn * KP_ };

    // ldmatrix per-lane base addresses
    const int q  = lane >> 3;
    const int rr = lane & 7;
    uint32_t abase[2];             // A: mt 0..1 (warp rows wm*32 .. +32)
#pragma unroll
    for (int mt = 0; mt < 2; mt++) {
        int row = wm * 32 + mt * 16 + (q & 1) * 8 + rr;
        abase[mt] = PK64(row, (q >> 1) * 16);
    }
    uint32_t bbase[4];             // W: np 0..3 (warp cols wn*64 .. +64)
#pragma unroll
    for (int np = 0; np < 4; np++) {
        int row = wn * 64 + np * 16 + (q >> 1) * 8 + rr;
        bbase[np] = PK64(row, (q & 1) * 16);
    }

    float acc[2][8][4];
#pragma unroll
    for (int mt = 0; mt < 2; mt++)
#pragma unroll
        for (int nt = 0; nt < 8; nt++)
#pragma unroll
            for (int i = 0; i < 4; i++) acc[mt][nt][i] = 0.0f;

#define GEMM_LOAD_CHUNK(sb, k0) do { \
    _Pragma("unroll") \
    for (int s = 0; s < 2; s++) { \
        _Pragma("unroll") \
        for (int j = 0; j < 2; j++) { \
            CP_ASYNC16((sb) + s * A_TILE_B + sdst[j], Asrc[s] + goff[j] + (k0)); \
            CP_ASYNC16((sb) + 2 * A_TILE_B + s * W_TILE_B + sdst[j], \
                       Wsrc[s] + goff[j] + (k0)); \
        } \
    } \
} while (0)

    // prologue: chunks 0..2 into stages 0..2
#pragma unroll
    for (int pk = 0; pk < 3; pk++) {
        GEMM_LOAD_CHUNK(smem_base + pk * STAGE_B, pk * BK);
        CP_COMMIT();
    }

    int sidx = 0;
    for (int k = 0; k < NCHUNK; k++) {
        CP_WAIT2();                // chunk k resident
        __syncthreads();

        const uint32_t stage = smem_base + sidx * STAGE_B;
        const uint32_t ast0 = stage;                   // A hi
        const uint32_t ast1 = stage + A_TILE_B;        // A lo
        const uint32_t wst0 = stage + 2 * A_TILE_B;    // W hi
        const uint32_t wst1 = wst0 + W_TILE_B;         // W lo

#pragma unroll
        for (int kk = 0; kk < 2; kk++) {
            uint32_t ah[2][4], al[2][4], bfr[4][4];
            // load A_hi + W_hi
#pragma unroll
            for (int mt = 0; mt < 2; mt++)
                ldsm_x4(ah[mt][0], ah[mt][1], ah[mt][2], ah[mt][3],
                        ast0 + SWZ128(abase[mt] + kk * 32));
#pragma unroll
            for (int np = 0; np < 4; np++)
                ldsm_x4(bfr[np][0], bfr[np][1], bfr[np][2], bfr[np][3],
                        wst0 + SWZ128(bbase[np] + kk * 32));
            // hi x hi
#pragma unroll
            for (int mt = 0; mt < 2; mt++)
#pragma unroll
                for (int np = 0; np < 4; np++) {
                    mma16816_f16(acc[mt][np * 2],     ah[mt], &bfr[np][0]);
                    mma16816_f16(acc[mt][np * 2 + 1], ah[mt], &bfr[np][2]);
                }
            // load A_lo; lo x hi
#pragma unroll
            for (int mt = 0; mt < 2; mt++)
                ldsm_x4(al[mt][0], al[mt][1], al[mt][2], al[mt][3],
                        ast1 + SWZ128(abase[mt] + kk * 32));
#pragma unroll
            for (int mt = 0; mt < 2; mt++)
#pragma unroll
                for (int np = 0; np < 4; np++) {
                    mma16816_f16(acc[mt][np * 2],     al[mt], &bfr[np][0]);
                    mma16816_f16(acc[mt][np * 2 + 1], al[mt], &bfr[np][2]);
                }
            // load W_lo over bfr; hi x lo
#pragma unroll
            for (int np = 0; np < 4; np++)
                ldsm_x4(bfr[np][0], bfr[np][1], bfr[np][2], bfr[np][3],
                        wst1 + SWZ128(bbase[np] + kk * 32));
#pragma unroll
            for (int mt = 0; mt < 2; mt++)
#pragma unroll
                for (int np = 0; np < 4; np++) {
                    mma16816_f16(acc[mt][np * 2],     ah[mt], &bfr[np][0]);
                    mma16816_f16(acc[mt][np * 2 + 1], ah[mt], &bfr[np][2]);
                }
        }
        __syncthreads();

        if (k + 3 < NCHUNK)
            GEMM_LOAD_CHUNK(smem_base + sidx * STAGE_B, (k + 3) * BK);
        CP_COMMIT();               // always commit to keep group accounting aligned
        sidx = (sidx == 2) ? 0 : sidx + 1;
    }

    const int mrow0 = bm + wm * 32;
    const int ncol0 = bn + wn * 64;
    const int lr = lane >> 2;
    const int lc = (lane & 3) * 2;
#pragma unroll
    for (int mt = 0; mt < 2; mt++) {
#pragma unroll
        for (int nt = 0; nt < 8; nt++) {
            int r = mrow0 + mt * 16 + lr;
            int c = ncol0 + nt * 8 + lc;
            float bx = __ldg(bias + c), by = __ldg(bias + c + 1);
            float2 v0 = make_float2(acc[mt][nt][0] * INV_SCALE + bx,
                                    acc[mt][nt][1] * INV_SCALE + by);
            float2 v1 = make_float2(acc[mt][nt][2] * INV_SCALE + bx,
                                    acc[mt][nt][3] * INV_SCALE + by);
            *(float2*)(g_d1 + (size_t)r * H_ + c)       = v0;
            *(float2*)(g_d1 + (size_t)(r + 8) * H_ + c) = v1;
        }
    }
}

// ---------------------------------------------------------------------------
// Kernel 2a: LIF layer-1 chains -> spike BITMASKS via ballot. 512 CTAs x 128.
// ---------------------------------------------------------------------------
__global__ __launch_bounds__(128) void lif1_kernel(
    const float* __restrict__ d1,
    const float* __restrict__ tau1)
{
    const int b    = blockIdx.x >> 1;
    const int half = blockIdx.x & 1;
    const int tid  = threadIdx.x;
    const int wl   = tid >> 5;
    const int lane = tid & 31;
    const int h0   = half * 512 + tid * 4;

    float4 tv = *(const float4*)(tau1 + h0);
    float a1[4], om[4], mem[4], spk[4];
    a1[0] = 1.0f / (1.0f + expf(-tv.x));
    a1[1] = 1.0f / (1.0f + expf(-tv.y));
    a1[2] = 1.0f / (1.0f + expf(-tv.z));
    a1[3] = 1.0f / (1.0f + expf(-tv.w));
#pragma unroll
    for (int j = 0; j < 4; j++) { om[j] = 1.0f - a1[j]; mem[j] = 0.0f; spk[j] = 0.0f; }

    const float* dp = d1 + (size_t)b * T_ * H_ + h0;
    uint32_t* mp = g_msk + (size_t)b * T_ * 32 + (half * 4 + wl) * 4;

    float4 nx0 = *(const float4*)dp;
    float4 nx1 = *(const float4*)(dp + H_);
    for (int t = 0; t < T_; t++) {
        float cur[4] = {nx0.x, nx0.y, nx0.z, nx0.w};
        nx0 = nx1;
        if (t + 2 < T_) nx1 = *(const float4*)(dp + (size_t)(t + 2) * H_);

#pragma unroll
        for (int j = 0; j < 4; j++) {
            mem[j] = mem[j] * a1[j] + om[j] * cur[j] - spk[j];
            spk[j] = (mem[j] > 1.0f) ? 1.0f : 0.0f;
        }
        uint32_t bits0 = __ballot_sync(0xffffffffu, mem[0] > 1.0f);
        uint32_t bits1 = __ballot_sync(0xffffffffu, mem[1] > 1.0f);
        uint32_t bits2 = __ballot_sync(0xffffffffu, mem[2] > 1.0f);
        uint32_t bits3 = __ballot_sync(0xffffffffu, mem[3] > 1.0f);
        if (lane < 4) {
            uint32_t w = (lane == 0) ? bits0 : (lane == 1) ? bits1
                       : (lane == 2) ? bits2 : bits3;
            mp[(size_t)t * 32 + lane] = w;
        }
    }
}

// ---------------------------------------------------------------------------
// Kernel 2b: d2^T = W2splits[32,1024] @ spk^T. Bitmask-expanded spikes.
// W2 in a 4-deep ring (race-free).
// ---------------------------------------------------------------------------
__global__ __launch_bounds__(256, 2)
void d2_gemm_kernel()
{
    extern __shared__ __align__(1024) char smem[];
    const uint32_t smem_base = smem_to_u32(smem);
    const int tid  = threadIdx.x;
    const int wid  = tid >> 5;
    const int lane = tid & 31;
    const int m0 = blockIdx.x * PB_ROWS;

    uint32_t ebase[2];
    const uint32_t* mrow[2];
#pragma unroll
    for (int i = 0; i < 2; i++) {
        int idx = tid + i * 256;
        int r = idx >> 1, wq = idx & 1;
        ebase[i] = (uint32_t)(r * 128 + wq * 64);
        mrow[i]  = g_msk + (size_t)(m0 + r) * 32 + wq;
    }

    const int wrow = tid >> 3, wunit = tid & 7;
    const uint32_t w_sdst = SWZ128(wrow * 128 + wunit * 16);
    const size_t   w_goff = (size_t)wrow * PB_K + wunit * 8;
    const uint32_t w2smem = smem_base + 2 * PB_SPKBUF;

    const int q  = lane >> 3;
    const int rr = lane & 7;
    uint32_t abyte[2];
#pragma unroll
    for (int mt = 0; mt < 2; mt++) {
        int row = mt * 16 + (q & 1) * 8 + rr;
        abyte[mt] = (uint32_t)(row * 128 + (q >> 1) * 16);
    }
    uint32_t bbyte[2];
#pragma unroll
    for (int np = 0; np < 2; np++) {
        int row = wid * 32 + np * 16 + (q >> 1) * 8 + rr;
        bbyte[np] = (uint32_t)(row * 128 + (q & 1) * 16);
    }

    float acc[2][4][4];
#pragma unroll
    for (int mt = 0; mt < 2; mt++)
#pragma unroll
        for (int nt = 0; nt < 4; nt++)
#pragma unroll
            for (int i = 0; i < 4; i++) acc[mt][nt][i] = 0.0f;

#pragma unroll
    for (int pk = 0; pk < 2; pk++) {
#pragma unroll
        for (int p = 0; p < 2; p++)
            CP_ASYNC16(w2smem + pk * PB_W2STAGE + p * PB_W2TILE + w_sdst,
                       &g_W2s[p][0] + w_goff + pk * PB_BK);
        CP_COMMIT();
    }
    uint32_t mcur[2];
#pragma unroll
    for (int i = 0; i < 2; i++) mcur[i] = mrow[i][0];

    for (int kc = 0; kc < PB_NCH; kc++) {
        __syncthreads();

        if (kc + 2 < PB_NCH) {
#pragma unroll
            for (int p = 0; p < 2; p++)
                CP_ASYNC16(w2smem + ((kc + 2) & 3) * PB_W2STAGE + p * PB_W2TILE + w_sdst,
                           &g_W2s[p][0] + w_goff + (kc + 2) * PB_BK);
        }
        CP_COMMIT();

        char* sb = smem + (kc & 1) * PB_SPKBUF;
#pragma unroll
        for (int i = 0; i < 2; i++) {
            uint32_t W = mcur[i];
#pragma unroll
            for (int g = 0; g < 4; g++) {
                uint4 u;
                u.x = expand2((W >> (g * 8 + 0)) & 3u);
                u.y = expand2((W >> (g * 8 + 2)) & 3u);
                u.z = expand2((W >> (g * 8 + 4)) & 3u);
                u.w = expand2((W >> (g * 8 + 6)) & 3u);
                *(uint4*)(sb + SWZ128(ebase[i] + g * 16)) = u;
            }
        }
        CP_WAIT2();
        __syncthreads();

        const uint32_t spkb = smem_base + (kc & 1) * PB_SPKBUF;
        const uint32_t w2b  = w2smem + (kc & 3) * PB_W2STAGE;
#pragma unroll
        for (int kk = 0; kk < 4; kk++) {
            uint32_t bf[4][2];
#pragma unroll
            for (int np = 0; np < 2; np++)
                ldsm_x4(bf[np * 2][0], bf[np * 2][1], bf[np * 2 + 1][0], bf[np * 2 + 1][1],
                        spkb + SWZ128(bbyte[np] + kk * 32));
#pragma unroll
            for (int p = 0; p < 2; p++) {
                uint32_t af[2][4];
#pragma unroll
                for (int mt = 0; mt < 2; mt++)
                    ldsm_x4(af[mt][0], af[mt][1], af[mt][2], af[mt][3],
                            w2b + p * PB_W2TILE + SWZ128(abyte[mt] + kk * 32));
#pragma unroll
                for (int mt = 0; mt < 2; mt++)
#pragma unroll
                    for (int nt = 0; nt < 4; nt++)
                        mma16816_bf16(acc[mt][nt], af[mt], bf[nt]);
            }
        }

        if (kc + 1 < PB_NCH) {
#pragma unroll
            for (int i = 0; i < 2; i++) mcur[i] = mrow[i][(kc + 1) * 2];
        }
    }

#pragma unroll
    for (int mt = 0; mt < 2; mt++) {
#pragma unroll
        for (int nt = 0; nt < 4; nt++) {
            int o  = mt * 16 + (lane >> 2);
            int n  = wid * 32 + nt * 8 + (lane & 3) * 2;
            size_t gm = (size_t)(m0 + n);
            g_d2[gm * 32 + o]           = acc[mt][nt][0];
            g_d2[(gm + 1) * 32 + o]     = acc[mt][nt][1];
            g_d2[gm * 32 + o + 8]       = acc[mt][nt][2];
            g_d2[(gm + 1) * 32 + o + 8] = acc[mt][nt][3];
        }
    }
}

// ---------------------------------------------------------------------------
// Kernel 2c: readout EMA + softmax accumulate (max-free; |mem2|<<88 so safe).
// ---------------------------------------------------------------------------
__global__ __launch_bounds__(256) void readout_kernel(
    const float* __restrict__ tau2,
    const float* __restrict__ b2,
    float* __restrict__ out)
{
    const int warp = threadIdx.x >> 5;
    const int lane = threadIdx.x & 31;
    const int b = blockIdx.x * 8 + warp;

    float a2 = 0.0f, oma2 = 0.0f, bb = 0.0f, mem2 = 0.0f, accv = 0.0f;
    if (lane < O_) {
        a2 = 1.0f / (1.0f + expf(-tau2[lane]));
        oma2 = 1.0f - a2;
        bb = b2[lane];
    }

    const float* dp = g_d2 + (size_t)b * T_ * 32;
    float v = dp[lane];
    for (int t = 0; t < T_; t++) {
        float vn = (t + 1 < T_) ? dp[(size_t)(t + 1) * 32 + lane] : 0.0f;
        if (lane < O_) mem2 = mem2 * a2 + oma2 * (v + bb);
        float e = (lane < O_) ? expf(mem2) : 0.0f;
        float s = e;
#pragma unroll
        for (int off = 16; off > 0; off >>= 1)
            s += __shfl_xor_sync(0xffffffffu, s, off);
        if (t > 10 && lane < O_) accv += e / s;
        v = vn;
    }
    if (lane < O_) out[b * O_ + lane] = accv;
}

// ---------------------------------------------------------------------------
extern "C" void kernel_launch(void* const* d_in, const int* in_sizes, int n_in,
                              void* d_out, int out_size)
{
    const float* input = (const float*)d_in[0];  // [B,T,D]
    const float* W1    = (const float*)d_in[1];  // [H,D]
    const float* b1    = (const float*)d_in[2];  // [H]
    const float* tau1  = (const float*)d_in[3];  // [H]
    const float* W2    = (const float*)d_in[4];  // [O,H]
    const float* b2    = (const float*)d_in[5];  // [O]
    const float* tau2  = (const float*)d_in[6];  // [O]
    float* out = (float*)d_out;                  // [B,O]

    cudaFuncSetAttribute(gemm_hmma_kernel,
                         cudaFuncAttributeMaxDynamicSharedMemorySize, SMEM_TOTAL);
    cudaFuncSetAttribute(d2_gemm_kernel,
                         cudaFuncAttributeMaxDynamicSharedMemorySize, PB_SMEM);

    __half *ah, *al, *wh, *wl;
    float *d1p;
    cudaGetSymbolAddress((void**)&ah,  g_Ah);
    cudaGetSymbolAddress((void**)&al,  g_Al);
    cudaGetSymbolAddress((void**)&wh,  g_Wh);
    cudaGetSymbolAddress((void**)&wl,  g_Wl);
    cudaGetSymbolAddress((void**)&d1p, g_d1);

    {
        long long ng = (long long)M_ * (KP_ / 8);
        int blocks = (int)((ng + 255) / 256);
        split2_kernel<<<blocks, 256>>>(input, M_, A_SCALE, ah, al);
    }
    {
        long long ng = (long long)H_ * (KP_ / 8);
        int blocks = (int)((ng + 255) / 256);
        split2_kernel<<<blocks, 256>>>(W1, H_, W_SCALE, wh, wl);
    }
    split_w2_kernel<<<(32 * PB_K + 255) / 256, 256>>>(W2);

    dim3 ggrid(H_ / BN, M_ / BM);  // (8, 500) = 4000 CTAs
    gemm_hmma_kernel<<<ggrid, 256, SMEM_TOTAL>>>(b1);

    lif1_kernel<<<2 * B_, 128>>>(d1p, tau1);
    d2_gemm_kernel<<<M_ / PB_ROWS, 256, PB_SMEM>>>();   // 250 CTAs
    readout_kernel<<<B_ / 8, 256>>>(tau2, b2, out);
}

// round 11
// speedup vs baseline: 1.0359x; 1.0359x over previous
#include <cuda_runtime.h>
#include <cuda_fp16.h>
#include <cuda_bf16.h>
#include <math_constants.h>
#include <cstdint>

// ---------------- shapes ----------------
#define B_  256
#define T_  250
#define D_  700
#define H_  1024
#define O_  20
#define M_  (B_ * T_)   // 64000
#define KP_ 704         // K padded to multiple of 64

// ---------------- main GEMM tiling (R7/R9-proven config; FROZEN) ----------------
#define BM 128
#define BN 64
#define BK 64
#define NCHUNK (KP_ / BK)              // 11
#define A_TILE_B (BM * BK * 2)         // 16384
#define W_TILE_B (BN * BK * 2)         // 8192
#define STAGE_B (2 * A_TILE_B + 2 * W_TILE_B)  // 49152
#define NSTAGE 2
#define SMEM_TOTAL (NSTAGE * STAGE_B)  // 98304 -> 2 CTAs/SM

#define A_SCALE 2048.0f
#define W_SCALE 64.0f
#define INV_SCALE (1.0f / (A_SCALE * W_SCALE))   // 2^-17, exact

// ---------------- phase-B (d2) GEMM tiling ----------------
#define PB_ROWS 128
#define PB_K    1024
#define PB_BK   64
#define PB_NCH  (PB_K / PB_BK)             // 16
#define PB_SPKBUF  (PB_ROWS * PB_BK * 2)   // 16384 per buffer
#define PB_W2TILE  (32 * PB_BK * 2)        // 4096 per split
#define PB_W2STAGE (2 * PB_W2TILE)         // 8192
#define PB_W2RING  4
#define PB_SMEM (2 * PB_SPKBUF + PB_W2RING * PB_W2STAGE)   // 65536

// ---------------- scratch (static device globals; no allocation) ----------------
__device__ float g_d1[(size_t)M_ * H_];
__device__ __half g_Ah[(size_t)M_ * KP_];
__device__ __half g_Al[(size_t)M_ * KP_];
__device__ __half g_Wh[(size_t)H_ * KP_];
__device__ __half g_Wl[(size_t)H_ * KP_];
__device__ uint32_t g_msk[(size_t)M_ * 32];            // spike bitmasks
__device__ __nv_bfloat16 g_W2s[2][32 * PB_K];          // W2 hi/lo bf16 splits (bit-permuted)
__device__ float g_d2[(size_t)M_ * 32];                // d2 (padded to 32 outputs)

// ---------------- family-safe PTX helpers ----------------
__device__ __forceinline__ uint32_t smem_to_u32(const void* smem_ptr) {
    uint32_t addr;
    asm("{ .reg .u64 tmp; cvta.to.shared.u64 tmp, %1; cvt.u32.u64 %0, tmp; }"
        : "=r"(addr) : "l"(smem_ptr));
    return addr;
}
#define CP_ASYNC16(dst_u32, src_ptr) \
    asm volatile("cp.async.cg.shared.global [%0], [%1], 16;" \
        :: "r"(dst_u32), "l"(src_ptr))
#define CP_COMMIT() asm volatile("cp.async.commit_group;" ::: "memory")
#define CP_WAIT1()  asm volatile("cp.async.wait_group 1;" ::: "memory")
#define CP_WAIT2()  asm volatile("cp.async.wait_group 2;" ::: "memory")

__device__ __forceinline__ void ldsm_x4(uint32_t& r0, uint32_t& r1,
                                        uint32_t& r2, uint32_t& r3, uint32_t addr) {
    asm volatile("ldmatrix.sync.aligned.m8n8.x4.shared.b16 {%0,%1,%2,%3}, [%4];"
        : "=r"(r0), "=r"(r1), "=r"(r2), "=r"(r3) : "r"(addr));
}
__device__ __forceinline__ void mma16816_f16(float* c, const uint32_t* a, const uint32_t* b) {
    asm volatile(
        "mma.sync.aligned.m16n8k16.row.col.f32.f16.f16.f32 "
        "{%0,%1,%2,%3}, {%4,%5,%6,%7}, {%8,%9}, {%0,%1,%2,%3};"
        : "+f"(c[0]), "+f"(c[1]), "+f"(c[2]), "+f"(c[3])
        : "r"(a[0]), "r"(a[1]), "r"(a[2]), "r"(a[3]), "r"(b[0]), "r"(b[1]));
}
__device__ __forceinline__ void mma16816_bf16(float* c, const uint32_t* a, const uint32_t* b) {
    asm volatile(
        "mma.sync.aligned.m16n8k16.row.col.f32.bf16.bf16.f32 "
        "{%0,%1,%2,%3}, {%4,%5,%6,%7}, {%8,%9}, {%0,%1,%2,%3};"
        : "+f"(c[0]), "+f"(c[1]), "+f"(c[2]), "+f"(c[3])
        : "r"(a[0]), "r"(a[1]), "r"(a[2]), "r"(a[3]), "r"(b[0]), "r"(b[1]));
}
#define SWZ128(o) ((o) ^ (((o) >> 3) & 0x70))

// expand 2 spike bits into packed bf16x2 (1.0f / 0.0f halves)
__device__ __forceinline__ uint32_t expand2(uint32_t b) {
    return ((b & 1u) * 0x3F80u) | ((b >> 1) * 0x3F800000u);
}

// ---------------------------------------------------------------------------
// Kernel 0: fp32 -> 2x fp16 split with pre-scale, 8 elems/thread.
// ---------------------------------------------------------------------------
__global__ void split2_kernel(const float* __restrict__ src, int rows, float scale,
                              __half* __restrict__ o0, __half* __restrict__ o1)
{
    const int GPR = KP_ / 8;  // 88
    long long idx = (long long)blockIdx.x * blockDim.x + threadIdx.x;
    if (idx >= (long long)rows * GPR) return;
    int m = (int)(idx / GPR);
    int g = (int)(idx % GPR);
    const float* sp = src + (size_t)m * D_ + g * 8;
    float4 f0 = *(const float4*)sp;                         // g*8 <= 696 < 700 always
    float4 f1 = (g < GPR - 1) ? *(const float4*)(sp + 4)
                              : make_float4(0.f, 0.f, 0.f, 0.f);
    float a[8] = {f0.x * scale, f0.y * scale, f0.z * scale, f0.w * scale,
                  f1.x * scale, f1.y * scale, f1.z * scale, f1.w * scale};
    unsigned short h0[8], h1[8];
#pragma unroll
    for (int i = 0; i < 8; i++) {
        __half hi = __float2half_rn(a[i]);
        __half lo = __float2half_rn(a[i] - __half2float(hi));
        h0[i] = __half_as_ushort(hi);
        h1[i] = __half_as_ushort(lo);
    }
    size_t off = (size_t)m * KP_ + g * 8;
    *(uint4*)(o0 + off) = make_uint4(
        (uint32_t)h0[1] << 16 | h0[0], (uint32_t)h0[3] << 16 | h0[2],
        (uint32_t)h0[5] << 16 | h0[4], (uint32_t)h0[7] << 16 | h0[6]);
    *(uint4*)(o1 + off) = make_uint4(
        (uint32_t)h1[1] << 16 | h1[0], (uint32_t)h1[3] << 16 | h1[2],
        (uint32_t)h1[5] << 16 | h1[4], (uint32_t)h1[7] << 16 | h1[6]);
}

// ---------------------------------------------------------------------------
// Kernel 0b: W2 -> 2x bf16 splits, PERMUTED to ballot bit order.
// h = (w>>2)*128 + l*4 + (w&3) for word w = p>>5, bit l = p&31.
// ---------------------------------------------------------------------------
__global__ void split_w2_kernel(const float* __restrict__ W2)
{
    int idx = blockIdx.x * blockDim.x + threadIdx.x;
    if (idx >= 32 * PB_K) return;
    int o = idx / PB_K;
    int p = idx % PB_K;
    int w = p >> 5, l = p & 31;
    int h = (w >> 2) * 128 + l * 4 + (w & 3);
    float v = (o < O_) ? W2[o * H_ + h] : 0.0f;
    __nv_bfloat16 hi = __float2bfloat16(v);
    __nv_bfloat16 lo = __float2bfloat16(v - __bfloat162float(hi));
    g_W2s[0][idx] = hi;
    g_W2s[1][idx] = lo;
}

// ---------------------------------------------------------------------------
// Kernel 1: HMMA fp16 GEMM, fp32 emulation via 3 cross-products.
// R7/R9-proven config, byte-for-byte: BM=128, BN=64, BK=64, 2-stage cp.async,
// 96KB smem -> 2 CTAs/SM. 8 warps in 4(m) x 2(n); warp tile 32x32.
// ---------------------------------------------------------------------------
__global__ __launch_bounds__(256, 2)
void gemm_hmma_kernel(const float* __restrict__ bias)
{
    extern __shared__ __align__(1024) char smem[];
    const uint32_t smem_base = smem_to_u32(smem);
    const int tid  = threadIdx.x;
    const int wid  = tid >> 5;
    const int lane = tid & 31;
    const int wm = wid >> 1;       // 0..3 (m)
    const int wn = wid & 1;        // 0..1 (n)
    const int bm = blockIdx.y * BM;
    const int bn = blockIdx.x * BN;

    uint32_t sdstA[4];
    size_t   goffA[4];
#pragma unroll
    for (int j = 0; j < 4; j++) {
        int c = tid + j * 256;
        int row = c >> 3, unit = c & 7;
        sdstA[j] = SWZ128(row * 128 + unit * 16);
        goffA[j] = (size_t)row * KP_ + unit * 8;
    }
    uint32_t sdstW[2];
    size_t   goffW[2];
#pragma unroll
    for (int j = 0; j < 2; j++) {
        int c = tid + j * 256;
        int row = c >> 3, unit = c & 7;
        sdstW[j] = SWZ128(row * 128 + unit * 16);
        goffW[j] = (size_t)row * KP_ + unit * 8;
    }
    const __half* Asrc[2] = { g_Ah + (size_t)bm * KP_, g_Al + (size_t)bm * KP_ };
    const __half* Wsrc[2] = { g_Wh + (size_t)bn * KP_, g_Wl + (size_t)bn * KP_ };

    const int q  = lane >> 3;
    const int rr = lane & 7;
    uint32_t abyte[2];
#pragma unroll
    for (int mt = 0; mt < 2; mt++) {
        int row = wm * 32 + mt * 16 + (q & 1) * 8 + rr;
        abyte[mt] = (uint32_t)(row * 128 + (q >> 1) * 16);
    }
    uint32_t bbyte[2];
#pragma unroll
    for (int np = 0; np < 2; np++) {
        int row = wn * 32 + np * 16 + (q >> 1) * 8 + rr;
        bbyte[np] = (uint32_t)(row * 128 + (q & 1) * 16);
    }

    float acc[2][4][4];
#pragma unroll
    for (int mt = 0; mt < 2; mt++)
#pragma unroll
        for (int nt = 0; nt < 4; nt++)
#pragma unroll
            for (int i = 0; i < 4; i++) acc[mt][nt][i] = 0.0f;

#define GEMM_LOAD_CHUNK(sb, k0) do { \
    _Pragma("unroll") \
    for (int s = 0; s < 2; s++) { \
        _Pragma("unroll") \
        for (int j = 0; j < 4; j++) \
            CP_ASYNC16((sb) + s * A_TILE_B + sdstA[j], Asrc[s] + goffA[j] + (k0)); \
        _Pragma("unroll") \
        for (int j = 0; j < 2; j++) \
            CP_ASYNC16((sb) + 2 * A_TILE_B + s * W_TILE_B + sdstW[j], \
                       Wsrc[s] + goffW[j] + (k0)); \
    } \
} while (0)

    GEMM_LOAD_CHUNK(smem_base, 0);
    CP_COMMIT();
    GEMM_LOAD_CHUNK(smem_base + STAGE_B, BK);
    CP_COMMIT();

    const int pa[3] = {0, 0, 1};
    const int pb[3] = {0, 1, 0};

    for (int k = 0; k < NCHUNK; k++) {
        CP_WAIT1();
        __syncthreads();

        const uint32_t stage = smem_base + (k & 1) * STAGE_B;
#pragma unroll
        for (int kk = 0; kk < 4; kk++) {
            uint32_t af[2][2][4];
            uint32_t bf[2][4][2];
#pragma unroll
            for (int s = 0; s < 2; s++) {
#pragma unroll
                for (int mt = 0; mt < 2; mt++)
                    ldsm_x4(af[s][mt][0], af[s][mt][1], af[s][mt][2], af[s][mt][3],
                            stage + s * A_TILE_B + SWZ128(abyte[mt] + kk * 32));
#pragma unroll
                for (int np = 0; np < 2; np++)
                    ldsm_x4(bf[s][np * 2][0], bf[s][np * 2][1],
                            bf[s][np * 2 + 1][0], bf[s][np * 2 + 1][1],
                            stage + 2 * A_TILE_B + s * W_TILE_B
                                  + SWZ128(bbyte[np] + kk * 32));
            }
#pragma unroll
            for (int p = 0; p < 3; p++)
#pragma unroll
                for (int mt = 0; mt < 2; mt++)
#pragma unroll
                    for (int nt = 0; nt < 4; nt++)
                        mma16816_f16(acc[mt][nt], af[pa[p]][mt], bf[pb[p]][nt]);
        }
        __syncthreads();

        if (k + NSTAGE < NCHUNK) {
            GEMM_LOAD_CHUNK(smem_base + (k & 1) * STAGE_B, (k + NSTAGE) * BK);
        }
        CP_COMMIT();
    }

    const int mrow0 = bm + wm * 32;
    const int ncol0 = bn + wn * 32;
    const int lr = lane >> 2;
    const int lc = (lane & 3) * 2;
#pragma unroll
    for (int mt = 0; mt < 2; mt++) {
#pragma unroll
        for (int nt = 0; nt < 4; nt++) {
            int r = mrow0 + mt * 16 + lr;
            int c = ncol0 + nt * 8 + lc;
            float bx = __ldg(bias + c), by = __ldg(bias + c + 1);
            float2 v0 = make_float2(acc[mt][nt][0] * INV_SCALE + bx,
                                    acc[mt][nt][1] * INV_SCALE + by);
            float2 v1 = make_float2(acc[mt][nt][2] * INV_SCALE + bx,
                                    acc[mt][nt][3] * INV_SCALE + by);
            *(float2*)(g_d1 + (size_t)r * H_ + c)       = v0;
            *(float2*)(g_d1 + (size_t)(r + 8) * H_ + c) = v1;
        }
    }
}

// ---------------------------------------------------------------------------
// Kernel 2a: LIF layer-1 chains -> spike BITMASKS via ballot.
// 1024 CTAs x 64 threads: CTA = (sample b, quarter of H). Word mapping
// preserved: global warp gw = quarter*2 + wl owns word gw*4+j holding at bit
// l the spike of h = gw*128 + l*4 + j.
// ---------------------------------------------------------------------------
__global__ __launch_bounds__(64) void lif1_kernel(
    const float* __restrict__ d1,
    const float* __restrict__ tau1)
{
    const int b       = blockIdx.x >> 2;
    const int quarter = blockIdx.x & 3;
    const int tid     = threadIdx.x;        // 0..63
    const int wl      = tid >> 5;           // 0..1
    const int lane    = tid & 31;
    const int h0      = quarter * 256 + tid * 4;

    float4 tv = *(const float4*)(tau1 + h0);
    float a1[4], om[4], mem[4], spk[4];
    a1[0] = 1.0f / (1.0f + expf(-tv.x));
    a1[1] = 1.0f / (1.0f + expf(-tv.y));
    a1[2] = 1.0f / (1.0f + expf(-tv.z));
    a1[3] = 1.0f / (1.0f + expf(-tv.w));
#pragma unroll
    for (int j = 0; j < 4; j++) { om[j] = 1.0f - a1[j]; mem[j] = 0.0f; spk[j] = 0.0f; }

    const float* dp = d1 + (size_t)b * T_ * H_ + h0;
    uint32_t* mp = g_msk + (size_t)b * T_ * 32 + (quarter * 2 + wl) * 4;

    float4 nx0 = *(const float4*)dp;
    float4 nx1 = *(const float4*)(dp + H_);
    for (int t = 0; t < T_; t++) {
        float cur[4] = {nx0.x, nx0.y, nx0.z, nx0.w};
        nx0 = nx1;
        if (t + 2 < T_) nx1 = *(const float4*)(dp + (size_t)(t + 2) * H_);

#pragma unroll
        for (int j = 0; j < 4; j++) {
            mem[j] = mem[j] * a1[j] + om[j] * cur[j] - spk[j];
            spk[j] = (mem[j] > 1.0f) ? 1.0f : 0.0f;
        }
        uint32_t bits0 = __ballot_sync(0xffffffffu, mem[0] > 1.0f);
        uint32_t bits1 = __ballot_sync(0xffffffffu, mem[1] > 1.0f);
        uint32_t bits2 = __ballot_sync(0xffffffffu, mem[2] > 1.0f);
        uint32_t bits3 = __ballot_sync(0xffffffffu, mem[3] > 1.0f);
        if (lane < 4) {
            uint32_t w = (lane == 0) ? bits0 : (lane == 1) ? bits1
                       : (lane == 2) ? bits2 : bits3;
            mp[(size_t)t * 32 + lane] = w;
        }
    }
}

// ---------------------------------------------------------------------------
// Kernel 2b: d2^T = W2splits[32,1024] @ spk^T. Bitmask-expanded spikes.
// PB_ROWS=128 -> 500 CTAs, 64KB smem, 2/SM (covers all 148 SMs).
// 8 warps x 16 rows each. W2 in a race-free 4-deep ring.
// ---------------------------------------------------------------------------
__global__ __launch_bounds__(256, 2)
void d2_gemm_kernel()
{
    extern __shared__ __align__(1024) char smem[];
    const uint32_t smem_base = smem_to_u32(smem);
    const int tid  = threadIdx.x;
    const int wid  = tid >> 5;
    const int lane = tid & 31;
    const int m0 = blockIdx.x * PB_ROWS;

    // expansion geometry: one entry per thread: row r = tid>>1, word wq = tid&1
    const int er = tid >> 1, ewq = tid & 1;
    const uint32_t ebase = (uint32_t)(er * 128 + ewq * 64);
    const uint32_t* mrow = g_msk + (size_t)(m0 + er) * 32 + ewq;

    // W2 cp.async geometry
    const int wrow = tid >> 3, wunit = tid & 7;
    const uint32_t w_sdst = SWZ128(wrow * 128 + wunit * 16);
    const size_t   w_goff = (size_t)wrow * PB_K + wunit * 8;
    const uint32_t w2smem = smem_base + 2 * PB_SPKBUF;

    // ldmatrix addresses
    const int q  = lane >> 3;
    const int rr = lane & 7;
    uint32_t abyte[2];                    // W2 (A-operand): mt 0..1
#pragma unroll
    for (int mt = 0; mt < 2; mt++) {
        int row = mt * 16 + (q & 1) * 8 + rr;
        abyte[mt] = (uint32_t)(row * 128 + (q >> 1) * 16);
    }
    // spikes (B-operand): warp covers 16 rows -> one ldsm_x4 per kk
    uint32_t bbyte;
    {
        int row = wid * 16 + (q >> 1) * 8 + rr;
        bbyte = (uint32_t)(row * 128 + (q & 1) * 16);
    }

    float acc[2][2][4];
#pragma unroll
    for (int mt = 0; mt < 2; mt++)
#pragma unroll
        for (int nt = 0; nt < 2; nt++)
#pragma unroll
            for (int i = 0; i < 4; i++) acc[mt][nt][i] = 0.0f;

    // prologue: W2 chunks 0,1 into ring slots 0,1
#pragma unroll
    for (int pk = 0; pk < 2; pk++) {
#pragma unroll
        for (int p = 0; p < 2; p++)
            CP_ASYNC16(w2smem + pk * PB_W2STAGE + p * PB_W2TILE + w_sdst,
                       &g_W2s[p][0] + w_goff + pk * PB_BK);
        CP_COMMIT();
    }
    uint32_t mcur = mrow[0];

    for (int kc = 0; kc < PB_NCH; kc++) {
        __syncthreads();   // all warps past iter kc-1: spkbuf(kc&1) and ring slot free

        // prefetch W2 chunk kc+2 into ring slot (kc+2)&3 (last read at kc-2)
        if (kc + 2 < PB_NCH) {
#pragma unroll
            for (int p = 0; p < 2; p++)
                CP_ASYNC16(w2smem + ((kc + 2) & 3) * PB_W2STAGE + p * PB_W2TILE + w_sdst,
                           &g_W2s[p][0] + w_goff + (kc + 2) * PB_BK);
        }
        CP_COMMIT();       // always commit

        // expand mask word -> spk bf16 tile
        char* sb = smem + (kc & 1) * PB_SPKBUF;
        {
            uint32_t W = mcur;
#pragma unroll
            for (int g = 0; g < 4; g++) {
                uint4 u;
                u.x = expand2((W >> (g * 8 + 0)) & 3u);
                u.y = expand2((W >> (g * 8 + 2)) & 3u);
                u.z = expand2((W >> (g * 8 + 4)) & 3u);
                u.w = expand2((W >> (g * 8 + 6)) & 3u);
                *(uint4*)(sb + SWZ128(ebase + g * 16)) = u;
            }
        }
        CP_WAIT2();        // W2 chunk kc resident (kc+1, kc+2 in flight)
        __syncthreads();   // expansion + W2 visible to all warps

        const uint32_t spkb = smem_base + (kc & 1) * PB_SPKBUF;
        const uint32_t w2b  = w2smem + (kc & 3) * PB_W2STAGE;
#pragma unroll
        for (int kk = 0; kk < 4; kk++) {
            uint32_t bf[2][2];
            ldsm_x4(bf[0][0], bf[0][1], bf[1][0], bf[1][1],
                    spkb + SWZ128(bbyte + kk * 32));
#pragma unroll
            for (int p = 0; p < 2; p++) {
                uint32_t af[2][4];
#pragma unroll
                for (int mt = 0; mt < 2; mt++)
                    ldsm_x4(af[mt][0], af[mt][1], af[mt][2], af[mt][3],
                            w2b + p * PB_W2TILE + SWZ128(abyte[mt] + kk * 32));
#pragma unroll
                for (int mt = 0; mt < 2; mt++)
#pragma unroll
                    for (int nt = 0; nt < 2; nt++)
                        mma16816_bf16(acc[mt][nt], af[mt], bf[nt]);
            }
        }

        if (kc + 1 < PB_NCH) mcur = mrow[(kc + 1) * 2];
    }

#pragma unroll
    for (int mt = 0; mt < 2; mt++) {
#pragma unroll
        for (int nt = 0; nt < 2; nt++) {
            int o  = mt * 16 + (lane >> 2);
            int n  = wid * 16 + nt * 8 + (lane & 3) * 2;
            size_t gm = (size_t)(m0 + n);
            g_d2[gm * 32 + o]           = acc[mt][nt][0];
            g_d2[(gm + 1) * 32 + o]     = acc[mt][nt][1];
            g_d2[gm * 32 + o + 8]       = acc[mt][nt][2];
            g_d2[(gm + 1) * 32 + o + 8] = acc[mt][nt][3];
        }
    }
}

// ---------------------------------------------------------------------------
// Kernel 2c: readout EMA + softmax accumulate (max-free; |mem2|<<88 so safe).
// ---------------------------------------------------------------------------
__global__ __launch_bounds__(256) void readout_kernel(
    const float* __restrict__ tau2,
    const float* __restrict__ b2,
    float* __restrict__ out)
{
    const int warp = threadIdx.x >> 5;
    const int lane = threadIdx.x & 31;
    const int b = blockIdx.x * 8 + warp;

    float a2 = 0.0f, oma2 = 0.0f, bb = 0.0f, mem2 = 0.0f, accv = 0.0f;
    if (lane < O_) {
        a2 = 1.0f / (1.0f + expf(-tau2[lane]));
        oma2 = 1.0f - a2;
        bb = b2[lane];
    }

    const float* dp = g_d2 + (size_t)b * T_ * 32;
    float v = dp[lane];
    for (int t = 0; t < T_; t++) {
        float vn = (t + 1 < T_) ? dp[(size_t)(t + 1) * 32 + lane] : 0.0f;
        if (lane < O_) mem2 = mem2 * a2 + oma2 * (v + bb);
        float e = (lane < O_) ? expf(mem2) : 0.0f;
        float s = e;
#pragma unroll
        for (int off = 16; off > 0; off >>= 1)
            s += __shfl_xor_sync(0xffffffffu, s, off);
        if (t > 10 && lane < O_) accv += e / s;
        v = vn;
    }
    if (lane < O_) out[b * O_ + lane] = accv;
}

// ---------------------------------------------------------------------------
extern "C" void kernel_launch(void* const* d_in, const int* in_sizes, int n_in,
                              void* d_out, int out_size)
{
    const float* input = (const float*)d_in[0];  // [B,T,D]
    const float* W1    = (const float*)d_in[1];  // [H,D]
    const float* b1    = (const float*)d_in[2];  // [H]
    const float* tau1  = (const float*)d_in[3];  // [H]
    const float* W2    = (const float*)d_in[4];  // [O,H]
    const float* b2    = (const float*)d_in[5];  // [O]
    const float* tau2  = (const float*)d_in[6];  // [O]
    float* out = (float*)d_out;                  // [B,O]

    cudaFuncSetAttribute(gemm_hmma_kernel,
                         cudaFuncAttributeMaxDynamicSharedMemorySize, SMEM_TOTAL);
    cudaFuncSetAttribute(d2_gemm_kernel,
                         cudaFuncAttributeMaxDynamicSharedMemorySize, PB_SMEM);

    __half *ah, *al, *wh, *wl;
    float *d1p;
    cudaGetSymbolAddress((void**)&ah,  g_Ah);
    cudaGetSymbolAddress((void**)&al,  g_Al);
    cudaGetSymbolAddress((void**)&wh,  g_Wh);
    cudaGetSymbolAddress((void**)&wl,  g_Wl);
    cudaGetSymbolAddress((void**)&d1p, g_d1);

    {
        long long ng = (long long)M_ * (KP_ / 8);
        int blocks = (int)((ng + 255) / 256);
        split2_kernel<<<blocks, 256>>>(input, M_, A_SCALE, ah, al);
    }
    {
        long long ng = (long long)H_ * (KP_ / 8);
        int blocks = (int)((ng + 255) / 256);
        split2_kernel<<<blocks, 256>>>(W1, H_, W_SCALE, wh, wl);
    }
    split_w2_kernel<<<(32 * PB_K + 255) / 256, 256>>>(W2);

    dim3 ggrid(H_ / BN, M_ / BM);  // (16, 500) = 8000 CTAs
    gemm_hmma_kernel<<<ggrid, 256, SMEM_TOTAL>>>(b1);

    lif1_kernel<<<4 * B_, 64>>>(d1p, tau1);
    d2_gemm_kernel<<<M_ / PB_ROWS, 256, PB_SMEM>>>();   // 500 CTAs
    readout_kernel<<<B_ / 8, 256>>>(tau2, b2, out);
}

// round 12
// speedup vs baseline: 1.1143x; 1.0757x over previous
#include <cuda_runtime.h>
#include <cuda_fp16.h>
#include <cuda_bf16.h>
#include <math_constants.h>
#include <cstdint>

// ---------------- shapes ----------------
#define B_  256
#define T_  250
#define D_  700
#define H_  1024
#define O_  20
#define M_  (B_ * T_)   // 64000
#define KP_ 704         // K padded to multiple of 64

// ---------------- main GEMM tiling (R7/R9-proven config; FROZEN) ----------------
#define BM 128
#define BN 64
#define BK 64
#define NCHUNK (KP_ / BK)              // 11
#define A_TILE_B (BM * BK * 2)         // 16384
#define W_TILE_B (BN * BK * 2)         // 8192
#define STAGE_B (2 * A_TILE_B + 2 * W_TILE_B)  // 49152
#define NSTAGE 2
#define SMEM_TOTAL (NSTAGE * STAGE_B)  // 98304 -> 2 CTAs/SM

#define A_SCALE 2048.0f
#define W_SCALE 64.0f
#define INV_SCALE (1.0f / (A_SCALE * W_SCALE))   // 2^-17, exact

// ---------------- phase-B (d2) GEMM tiling (R9-proven) ----------------
#define PB_ROWS 256
#define PB_K    1024
#define PB_BK   64
#define PB_NCH  (PB_K / PB_BK)             // 16
#define PB_SPKBUF  (PB_ROWS * PB_BK * 2)   // 32768 per buffer
#define PB_W2TILE  (32 * PB_BK * 2)        // 4096 per split
#define PB_W2STAGE (2 * PB_W2TILE)         // 8192
#define PB_W2RING  4
#define PB_SMEM (2 * PB_SPKBUF + PB_W2RING * PB_W2STAGE)   // 98304

// ---------------- scratch (static device globals; no allocation) ----------------
__device__ float g_d1[(size_t)M_ * H_];
__device__ __half g_Ah[(size_t)M_ * KP_];
__device__ __half g_Al[(size_t)M_ * KP_];
__device__ __half g_Wh[(size_t)H_ * KP_];
__device__ __half g_Wl[(size_t)H_ * KP_];
__device__ uint32_t g_msk[(size_t)M_ * 32];            // spike bitmasks
__device__ __nv_bfloat16 g_W2s[2][32 * PB_K];          // W2 hi/lo bf16 splits (bit-permuted)
__device__ float g_d2[(size_t)M_ * 32];                // d2 (padded to 32 outputs)

// ---------------- family-safe PTX helpers ----------------
__device__ __forceinline__ uint32_t smem_to_u32(const void* smem_ptr) {
    uint32_t addr;
    asm("{ .reg .u64 tmp; cvta.to.shared.u64 tmp, %1; cvt.u32.u64 %0, tmp; }"
        : "=r"(addr) : "l"(smem_ptr));
    return addr;
}
#define CP_ASYNC16(dst_u32, src_ptr) \
    asm volatile("cp.async.cg.shared.global [%0], [%1], 16;" \
        :: "r"(dst_u32), "l"(src_ptr))
#define CP_COMMIT() asm volatile("cp.async.commit_group;" ::: "memory")
#define CP_WAIT1()  asm volatile("cp.async.wait_group 1;" ::: "memory")
#define CP_WAIT2()  asm volatile("cp.async.wait_group 2;" ::: "memory")

__device__ __forceinline__ void ldsm_x4(uint32_t& r0, uint32_t& r1,
                                        uint32_t& r2, uint32_t& r3, uint32_t addr) {
    asm volatile("ldmatrix.sync.aligned.m8n8.x4.shared.b16 {%0,%1,%2,%3}, [%4];"
        : "=r"(r0), "=r"(r1), "=r"(r2), "=r"(r3) : "r"(addr));
}
__device__ __forceinline__ void mma16816_f16(float* c, const uint32_t* a, const uint32_t* b) {
    asm volatile(
        "mma.sync.aligned.m16n8k16.row.col.f32.f16.f16.f32 "
        "{%0,%1,%2,%3}, {%4,%5,%6,%7}, {%8,%9}, {%0,%1,%2,%3};"
        : "+f"(c[0]), "+f"(c[1]), "+f"(c[2]), "+f"(c[3])
        : "r"(a[0]), "r"(a[1]), "r"(a[2]), "r"(a[3]), "r"(b[0]), "r"(b[1]));
}
__device__ __forceinline__ void mma16816_bf16(float* c, const uint32_t* a, const uint32_t* b) {
    asm volatile(
        "mma.sync.aligned.m16n8k16.row.col.f32.bf16.bf16.f32 "
        "{%0,%1,%2,%3}, {%4,%5,%6,%7}, {%8,%9}, {%0,%1,%2,%3};"
        : "+f"(c[0]), "+f"(c[1]), "+f"(c[2]), "+f"(c[3])
        : "r"(a[0]), "r"(a[1]), "r"(a[2]), "r"(a[3]), "r"(b[0]), "r"(b[1]));
}
#define SWZ128(o) ((o) ^ (((o) >> 3) & 0x70))

// expand 2 spike bits into packed bf16x2 (1.0f / 0.0f halves)
__device__ __forceinline__ uint32_t expand2(uint32_t b) {
    return ((b & 1u) * 0x3F80u) | ((b >> 1) * 0x3F800000u);
}

// ---------------------------------------------------------------------------
// Kernel 0: fp32 -> 2x fp16 split with pre-scale, 8 elems/thread.
// __ldcs on source (read-once stream).
// ---------------------------------------------------------------------------
__global__ void split2_kernel(const float* __restrict__ src, int rows, float scale,
                              __half* __restrict__ o0, __half* __restrict__ o1)
{
    const int GPR = KP_ / 8;  // 88
    long long idx = (long long)blockIdx.x * blockDim.x + threadIdx.x;
    if (idx >= (long long)rows * GPR) return;
    int m = (int)(idx / GPR);
    int g = (int)(idx % GPR);
    const float* sp = src + (size_t)m * D_ + g * 8;
    float4 f0 = __ldcs((const float4*)sp);                  // g*8 <= 696 < 700 always
    float4 f1 = (g < GPR - 1) ? __ldcs((const float4*)(sp + 4))
                              : make_float4(0.f, 0.f, 0.f, 0.f);
    float a[8] = {f0.x * scale, f0.y * scale, f0.z * scale, f0.w * scale,
                  f1.x * scale, f1.y * scale, f1.z * scale, f1.w * scale};
    unsigned short h0[8], h1[8];
#pragma unroll
    for (int i = 0; i < 8; i++) {
        __half hi = __float2half_rn(a[i]);
        __half lo = __float2half_rn(a[i] - __half2float(hi));
        h0[i] = __half_as_ushort(hi);
        h1[i] = __half_as_ushort(lo);
    }
    size_t off = (size_t)m * KP_ + g * 8;
    *(uint4*)(o0 + off) = make_uint4(
        (uint32_t)h0[1] << 16 | h0[0], (uint32_t)h0[3] << 16 | h0[2],
        (uint32_t)h0[5] << 16 | h0[4], (uint32_t)h0[7] << 16 | h0[6]);
    *(uint4*)(o1 + off) = make_uint4(
        (uint32_t)h1[1] << 16 | h1[0], (uint32_t)h1[3] << 16 | h1[2],
        (uint32_t)h1[5] << 16 | h1[4], (uint32_t)h1[7] << 16 | h1[6]);
}

// ---------------------------------------------------------------------------
// Kernel 0b: W2 -> 2x bf16 splits, PERMUTED to ballot bit order.
// h = (w>>2)*128 + l*4 + (w&3) for word w = p>>5, bit l = p&31.
// ---------------------------------------------------------------------------
__global__ void split_w2_kernel(const float* __restrict__ W2)
{
    int idx = blockIdx.x * blockDim.x + threadIdx.x;
    if (idx >= 32 * PB_K) return;
    int o = idx / PB_K;
    int p = idx % PB_K;
    int w = p >> 5, l = p & 31;
    int h = (w >> 2) * 128 + l * 4 + (w & 3);
    float v = (o < O_) ? W2[o * H_ + h] : 0.0f;
    __nv_bfloat16 hi = __float2bfloat16(v);
    __nv_bfloat16 lo = __float2bfloat16(v - __bfloat162float(hi));
    g_W2s[0][idx] = hi;
    g_W2s[1][idx] = lo;
}

// ---------------------------------------------------------------------------
// Kernel 1: HMMA fp16 GEMM, fp32 emulation via 3 cross-products.
// R7/R9-proven config, byte-for-byte.
// ---------------------------------------------------------------------------
__global__ __launch_bounds__(256, 2)
void gemm_hmma_kernel(const float* __restrict__ bias)
{
    extern __shared__ __align__(1024) char smem[];
    const uint32_t smem_base = smem_to_u32(smem);
    const int tid  = threadIdx.x;
    const int wid  = tid >> 5;
    const int lane = tid & 31;
    const int wm = wid >> 1;       // 0..3 (m)
    const int wn = wid & 1;        // 0..1 (n)
    const int bm = blockIdx.y * BM;
    const int bn = blockIdx.x * BN;

    uint32_t sdstA[4];
    size_t   goffA[4];
#pragma unroll
    for (int j = 0; j < 4; j++) {
        int c = tid + j * 256;
        int row = c >> 3, unit = c & 7;
        sdstA[j] = SWZ128(row * 128 + unit * 16);
        goffA[j] = (size_t)row * KP_ + unit * 8;
    }
    uint32_t sdstW[2];
    size_t   goffW[2];
#pragma unroll
    for (int j = 0; j < 2; j++) {
        int c = tid + j * 256;
        int row = c >> 3, unit = c & 7;
        sdstW[j] = SWZ128(row * 128 + unit * 16);
        goffW[j] = (size_t)row * KP_ + unit * 8;
    }
    const __half* Asrc[2] = { g_Ah + (size_t)bm * KP_, g_Al + (size_t)bm * KP_ };
    const __half* Wsrc[2] = { g_Wh + (size_t)bn * KP_, g_Wl + (size_t)bn * KP_ };

    const int q  = lane >> 3;
    const int rr = lane & 7;
    uint32_t abyte[2];
#pragma unroll
    for (int mt = 0; mt < 2; mt++) {
        int row = wm * 32 + mt * 16 + (q & 1) * 8 + rr;
        abyte[mt] = (uint32_t)(row * 128 + (q >> 1) * 16);
    }
    uint32_t bbyte[2];
#pragma unroll
    for (int np = 0; np < 2; np++) {
        int row = wn * 32 + np * 16 + (q >> 1) * 8 + rr;
        bbyte[np] = (uint32_t)(row * 128 + (q & 1) * 16);
    }

    float acc[2][4][4];
#pragma unroll
    for (int mt = 0; mt < 2; mt++)
#pragma unroll
        for (int nt = 0; nt < 4; nt++)
#pragma unroll
            for (int i = 0; i < 4; i++) acc[mt][nt][i] = 0.0f;

#define GEMM_LOAD_CHUNK(sb, k0) do { \
    _Pragma("unroll") \
    for (int s = 0; s < 2; s++) { \
        _Pragma("unroll") \
        for (int j = 0; j < 4; j++) \
            CP_ASYNC16((sb) + s * A_TILE_B + sdstA[j], Asrc[s] + goffA[j] + (k0)); \
        _Pragma("unroll") \
        for (int j = 0; j < 2; j++) \
            CP_ASYNC16((sb) + 2 * A_TILE_B + s * W_TILE_B + sdstW[j], \
                       Wsrc[s] + goffW[j] + (k0)); \
    } \
} while (0)

    GEMM_LOAD_CHUNK(smem_base, 0);
    CP_COMMIT();
    GEMM_LOAD_CHUNK(smem_base + STAGE_B, BK);
    CP_COMMIT();

    const int pa[3] = {0, 0, 1};
    const int pb[3] = {0, 1, 0};

    for (int k = 0; k < NCHUNK; k++) {
        CP_WAIT1();
        __syncthreads();

        const uint32_t stage = smem_base + (k & 1) * STAGE_B;
#pragma unroll
        for (int kk = 0; kk < 4; kk++) {
            uint32_t af[2][2][4];
            uint32_t bf[2][4][2];
#pragma unroll
            for (int s = 0; s < 2; s++) {
#pragma unroll
                for (int mt = 0; mt < 2; mt++)
                    ldsm_x4(af[s][mt][0], af[s][mt][1], af[s][mt][2], af[s][mt][3],
                            stage + s * A_TILE_B + SWZ128(abyte[mt] + kk * 32));
#pragma unroll
                for (int np = 0; np < 2; np++)
                    ldsm_x4(bf[s][np * 2][0], bf[s][np * 2][1],
                            bf[s][np * 2 + 1][0], bf[s][np * 2 + 1][1],
                            stage + 2 * A_TILE_B + s * W_TILE_B
                                  + SWZ128(bbyte[np] + kk * 32));
            }
#pragma unroll
            for (int p = 0; p < 3; p++)
#pragma unroll
                for (int mt = 0; mt < 2; mt++)
#pragma unroll
                    for (int nt = 0; nt < 4; nt++)
                        mma16816_f16(acc[mt][nt], af[pa[p]][mt], bf[pb[p]][nt]);
        }
        __syncthreads();

        if (k + NSTAGE < NCHUNK) {
            GEMM_LOAD_CHUNK(smem_base + (k & 1) * STAGE_B, (k + NSTAGE) * BK);
        }
        CP_COMMIT();
    }

    const int mrow0 = bm + wm * 32;
    const int ncol0 = bn + wn * 32;
    const int lr = lane >> 2;
    const int lc = (lane & 3) * 2;
#pragma unroll
    for (int mt = 0; mt < 2; mt++) {
#pragma unroll
        for (int nt = 0; nt < 4; nt++) {
            int r = mrow0 + mt * 16 + lr;
            int c = ncol0 + nt * 8 + lc;
            float bx = __ldg(bias + c), by = __ldg(bias + c + 1);
            float2 v0 = make_float2(acc[mt][nt][0] * INV_SCALE + bx,
                                    acc[mt][nt][1] * INV_SCALE + by);
            float2 v1 = make_float2(acc[mt][nt][2] * INV_SCALE + bx,
                                    acc[mt][nt][3] * INV_SCALE + by);
            *(float2*)(g_d1 + (size_t)r * H_ + c)       = v0;
            *(float2*)(g_d1 + (size_t)(r + 8) * H_ + c) = v1;
        }
    }
}

// ---------------------------------------------------------------------------
// Kernel 2a: LIF layer-1 chains -> spike BITMASKS via ballot. 512 CTAs x 128.
// R9 config + 4-deep register prefetch ring + __ldcs streaming loads.
// word w = gwarp*4 + j holds at bit l the spike of h = gwarp*128 + l*4 + j.
// ---------------------------------------------------------------------------
__global__ __launch_bounds__(128) void lif1_kernel(
    const float* __restrict__ d1,
    const float* __restrict__ tau1)
{
    const int b    = blockIdx.x >> 1;
    const int half = blockIdx.x & 1;
    const int tid  = threadIdx.x;
    const int wl   = tid >> 5;
    const int lane = tid & 31;
    const int h0   = half * 512 + tid * 4;

    float4 tv = *(const float4*)(tau1 + h0);
    float a1[4], om[4], mem[4], spk[4];
    a1[0] = 1.0f / (1.0f + expf(-tv.x));
    a1[1] = 1.0f / (1.0f + expf(-tv.y));
    a1[2] = 1.0f / (1.0f + expf(-tv.z));
    a1[3] = 1.0f / (1.0f + expf(-tv.w));
#pragma unroll
    for (int j = 0; j < 4; j++) { om[j] = 1.0f - a1[j]; mem[j] = 0.0f; spk[j] = 0.0f; }

    const float* dp = d1 + (size_t)b * T_ * H_ + h0;
    uint32_t* mp = g_msk + (size_t)b * T_ * 32 + (half * 4 + wl) * 4;

    // 4-deep prefetch ring
    float4 pre[4];
#pragma unroll
    for (int i = 0; i < 4; i++)
        pre[i] = __ldcs((const float4*)(dp + (size_t)i * H_));

#pragma unroll 4
    for (int t = 0; t < T_; t++) {
        float4 c = pre[t & 3];
        if (t + 4 < T_)
            pre[t & 3] = __ldcs((const float4*)(dp + (size_t)(t + 4) * H_));
        float cur[4] = {c.x, c.y, c.z, c.w};

#pragma unroll
        for (int j = 0; j < 4; j++) {
            mem[j] = mem[j] * a1[j] + om[j] * cur[j] - spk[j];
            spk[j] = (mem[j] > 1.0f) ? 1.0f : 0.0f;
        }
        uint32_t bits0 = __ballot_sync(0xffffffffu, mem[0] > 1.0f);
        uint32_t bits1 = __ballot_sync(0xffffffffu, mem[1] > 1.0f);
        uint32_t bits2 = __ballot_sync(0xffffffffu, mem[2] > 1.0f);
        uint32_t bits3 = __ballot_sync(0xffffffffu, mem[3] > 1.0f);
        if (lane < 4) {
            uint32_t w = (lane == 0) ? bits0 : (lane == 1) ? bits1
                       : (lane == 2) ? bits2 : bits3;
            mp[(size_t)t * 32 + lane] = w;
        }
    }
}

// ---------------------------------------------------------------------------
// Kernel 2b: d2^T = W2splits[32,1024] @ spk^T. Bitmask-expanded spikes.
// R9-proven: PB_ROWS=256 -> 250 CTAs, 96KB smem, W2 in race-free 4-deep ring.
// ---------------------------------------------------------------------------
__global__ __launch_bounds__(256, 2)
void d2_gemm_kernel()
{
    extern __shared__ __align__(1024) char smem[];
    const uint32_t smem_base = smem_to_u32(smem);
    const int tid  = threadIdx.x;
    const int wid  = tid >> 5;
    const int lane = tid & 31;
    const int m0 = blockIdx.x * PB_ROWS;

    uint32_t ebase[2];
    const uint32_t* mrow[2];
#pragma unroll
    for (int i = 0; i < 2; i++) {
        int idx = tid + i * 256;
        int r = idx >> 1, wq = idx & 1;
        ebase[i] = (uint32_t)(r * 128 + wq * 64);
        mrow[i]  = g_msk + (size_t)(m0 + r) * 32 + wq;
    }

    const int wrow = tid >> 3, wunit = tid & 7;
    const uint32_t w_sdst = SWZ128(wrow * 128 + wunit * 16);
    const size_t   w_goff = (size_t)wrow * PB_K + wunit * 8;
    const uint32_t w2smem = smem_base + 2 * PB_SPKBUF;

    const int q  = lane >> 3;
    const int rr = lane & 7;
    uint32_t abyte[2];
#pragma unroll
    for (int mt = 0; mt < 2; mt++) {
        int row = mt * 16 + (q & 1) * 8 + rr;
        abyte[mt] = (uint32_t)(row * 128 + (q >> 1) * 16);
    }
    uint32_t bbyte[2];
#pragma unroll
    for (int np = 0; np < 2; np++) {
        int row = wid * 32 + np * 16 + (q >> 1) * 8 + rr;
        bbyte[np] = (uint32_t)(row * 128 + (q & 1) * 16);
    }

    float acc[2][4][4];
#pragma unroll
    for (int mt = 0; mt < 2; mt++)
#pragma unroll
        for (int nt = 0; nt < 4; nt++)
#pragma unroll
            for (int i = 0; i < 4; i++) acc[mt][nt][i] = 0.0f;

#pragma unroll
    for (int pk = 0; pk < 2; pk++) {
#pragma unroll
        for (int p = 0; p < 2; p++)
            CP_ASYNC16(w2smem + pk * PB_W2STAGE + p * PB_W2TILE + w_sdst,
                       &g_W2s[p][0] + w_goff + pk * PB_BK);
        CP_COMMIT();
    }
    uint32_t mcur[2];
#pragma unroll
    for (int i = 0; i < 2; i++) mcur[i] = mrow[i][0];

    for (int kc = 0; kc < PB_NCH; kc++) {
        __syncthreads();

        if (kc + 2 < PB_NCH) {
#pragma unroll
            for (int p = 0; p < 2; p++)
                CP_ASYNC16(w2smem + ((kc + 2) & 3) * PB_W2STAGE + p * PB_W2TILE + w_sdst,
                           &g_W2s[p][0] + w_goff + (kc + 2) * PB_BK);
        }
        CP_COMMIT();

        char* sb = smem + (kc & 1) * PB_SPKBUF;
#pragma unroll
        for (int i = 0; i < 2; i++) {
            uint32_t W = mcur[i];
#pragma unroll
            for (int g = 0; g < 4; g++) {
                uint4 u;
                u.x = expand2((W >> (g * 8 + 0)) & 3u);
                u.y = expand2((W >> (g * 8 + 2)) & 3u);
                u.z = expand2((W >> (g * 8 + 4)) & 3u);
                u.w = expand2((W >> (g * 8 + 6)) & 3u);
                *(uint4*)(sb + SWZ128(ebase[i] + g * 16)) = u;
            }
        }
        CP_WAIT2();
        __syncthreads();

        const uint32_t spkb = smem_base + (kc & 1) * PB_SPKBUF;
        const uint32_t w2b  = w2smem + (kc & 3) * PB_W2STAGE;
#pragma unroll
        for (int kk = 0; kk < 4; kk++) {
            uint32_t bf[4][2];
#pragma unroll
            for (int np = 0; np < 2; np++)
                ldsm_x4(bf[np * 2][0], bf[np * 2][1], bf[np * 2 + 1][0], bf[np * 2 + 1][1],
                        spkb + SWZ128(bbyte[np] + kk * 32));
#pragma unroll
            for (int p = 0; p < 2; p++) {
                uint32_t af[2][4];
#pragma unroll
                for (int mt = 0; mt < 2; mt++)
                    ldsm_x4(af[mt][0], af[mt][1], af[mt][2], af[mt][3],
                            w2b + p * PB_W2TILE + SWZ128(abyte[mt] + kk * 32));
#pragma unroll
                for (int mt = 0; mt < 2; mt++)
#pragma unroll
                    for (int nt = 0; nt < 4; nt++)
                        mma16816_bf16(acc[mt][nt], af[mt], bf[nt]);
            }
        }

        if (kc + 1 < PB_NCH) {
#pragma unroll
            for (int i = 0; i < 2; i++) mcur[i] = mrow[i][(kc + 1) * 2];
        }
    }

#pragma unroll
    for (int mt = 0; mt < 2; mt++) {
#pragma unroll
        for (int nt = 0; nt < 4; nt++) {
            int o  = mt * 16 + (lane >> 2);
            int n  = wid * 32 + nt * 8 + (lane & 3) * 2;
            size_t gm = (size_t)(m0 + n);
            g_d2[gm * 32 + o]           = acc[mt][nt][0];
            g_d2[(gm + 1) * 32 + o]     = acc[mt][nt][1];
            g_d2[gm * 32 + o + 8]       = acc[mt][nt][2];
            g_d2[(gm + 1) * 32 + o + 8] = acc[mt][nt][3];
        }
    }
}

// ---------------------------------------------------------------------------
// Kernel 2c: readout EMA + softmax accumulate (max-free; |mem2|<<88 so safe).
// ---------------------------------------------------------------------------
__global__ __launch_bounds__(256) void readout_kernel(
    const float* __restrict__ tau2,
    const float* __restrict__ b2,
    float* __restrict__ out)
{
    const int warp = threadIdx.x >> 5;
    const int lane = threadIdx.x & 31;
    const int b = blockIdx.x * 8 + warp;

    float a2 = 0.0f, oma2 = 0.0f, bb = 0.0f, mem2 = 0.0f, accv = 0.0f;
    if (lane < O_) {
        a2 = 1.0f / (1.0f + expf(-tau2[lane]));
        oma2 = 1.0f - a2;
        bb = b2[lane];
    }

    const float* dp = g_d2 + (size_t)b * T_ * 32;
    float v = dp[lane];
    for (int t = 0; t < T_; t++) {
        float vn = (t + 1 < T_) ? dp[(size_t)(t + 1) * 32 + lane] : 0.0f;
        if (lane < O_) mem2 = mem2 * a2 + oma2 * (v + bb);
        float e = (lane < O_) ? expf(mem2) : 0.0f;
        float s = e;
#pragma unroll
        for (int off = 16; off > 0; off >>= 1)
            s += __shfl_xor_sync(0xffffffffu, s, off);
        if (t > 10 && lane < O_) accv += e / s;
        v = vn;
    }
    if (lane < O_) out[b * O_ + lane] = accv;
}

// ---------------------------------------------------------------------------
extern "C" void kernel_launch(void* const* d_in, const int* in_sizes, int n_in,
                              void* d_out, int out_size)
{
    const float* input = (const float*)d_in[0];  // [B,T,D]
    const float* W1    = (const float*)d_in[1];  // [H,D]
    const float* b1    = (const float*)d_in[2];  // [H]
    const float* tau1  = (const float*)d_in[3];  // [H]
    const float* W2    = (const float*)d_in[4];  // [O,H]
    const float* b2    = (const float*)d_in[5];  // [O]
    const float* tau2  = (const float*)d_in[6];  // [O]
    float* out = (float*)d_out;                  // [B,O]

    cudaFuncSetAttribute(gemm_hmma_kernel,
                         cudaFuncAttributeMaxDynamicSharedMemorySize, SMEM_TOTAL);
    cudaFuncSetAttribute(d2_gemm_kernel,
                         cudaFuncAttributeMaxDynamicSharedMemorySize, PB_SMEM);

    __half *ah, *al, *wh, *wl;
    float *d1p;
    cudaGetSymbolAddress((void**)&ah,  g_Ah);
    cudaGetSymbolAddress((void**)&al,  g_Al);
    cudaGetSymbolAddress((void**)&wh,  g_Wh);
    cudaGetSymbolAddress((void**)&wl,  g_Wl);
    cudaGetSymbolAddress((void**)&d1p, g_d1);

    {
        long long ng = (long long)M_ * (KP_ / 8);
        int blocks = (int)((ng + 255) / 256);
        split2_kernel<<<blocks, 256>>>(input, M_, A_SCALE, ah, al);
    }
    {
        long long ng = (long long)H_ * (KP_ / 8);
        int blocks = (int)((ng + 255) / 256);
        split2_kernel<<<blocks, 256>>>(W1, H_, W_SCALE, wh, wl);
    }
    split_w2_kernel<<<(32 * PB_K + 255) / 256, 256>>>(W2);

    dim3 ggrid(H_ / BN, M_ / BM);  // (16, 500) = 8000 CTAs
    gemm_hmma_kernel<<<ggrid, 256, SMEM_TOTAL>>>(b1);

    lif1_kernel<<<2 * B_, 128>>>(d1p, tau1);
    d2_gemm_kernel<<<M_ / PB_ROWS, 256, PB_SMEM>>>();   // 250 CTAs
    readout_kernel<<<B_ / 8, 256>>>(tau2, b2, out);
}

// round 13
// speedup vs baseline: 1.1212x; 1.0062x over previous
#include <cuda_runtime.h>
#include <cuda_fp16.h>
#include <cuda_bf16.h>
#include <math_constants.h>
#include <cstdint>

// ---------------- shapes ----------------
#define B_  256
#define T_  250
#define D_  700
#define H_  1024
#define O_  20
#define M_  (B_ * T_)   // 64000
#define KP_ 704         // K padded to multiple of 64

// ---------------- main GEMM tiling (R7/R9-proven config; FROZEN) ----------------
#define BM 128
#define BN 64
#define BK 64
#define NCHUNK (KP_ / BK)              // 11
#define A_TILE_B (BM * BK * 2)         // 16384
#define W_TILE_B (BN * BK * 2)         // 8192
#define STAGE_B (2 * A_TILE_B + 2 * W_TILE_B)  // 49152
#define NSTAGE 2
#define SMEM_TOTAL (NSTAGE * STAGE_B)  // 98304 -> 2 CTAs/SM

#define A_SCALE 2048.0f
#define W_SCALE 64.0f
#define INV_SCALE (1.0f / (A_SCALE * W_SCALE))   // 2^-17, exact

// ---------------- phase-B (d2) GEMM tiling (R9-proven) ----------------
#define PB_ROWS 256
#define PB_K    1024
#define PB_BK   64
#define PB_NCH  (PB_K / PB_BK)             // 16
#define PB_SPKBUF  (PB_ROWS * PB_BK * 2)   // 32768 per buffer
#define PB_W2TILE  (32 * PB_BK * 2)        // 4096 per split
#define PB_W2STAGE (2 * PB_W2TILE)         // 8192
#define PB_W2RING  4
#define PB_SMEM (2 * PB_SPKBUF + PB_W2RING * PB_W2STAGE)   // 98304

// ---------------- scratch (static device globals; no allocation) ----------------
__device__ float g_d1[(size_t)M_ * H_];
__device__ __half g_Ah[(size_t)M_ * KP_];
__device__ __half g_Al[(size_t)M_ * KP_];
__device__ __half g_Wh[(size_t)H_ * KP_];
__device__ __half g_Wl[(size_t)H_ * KP_];
__device__ uint32_t g_msk[(size_t)M_ * 32];            // spike bitmasks
__device__ __nv_bfloat16 g_W2s[2][32 * PB_K];          // W2 hi/lo bf16 splits (bit-permuted)
__device__ float g_d2[(size_t)M_ * 32];                // d2 (padded to 32 outputs)

// ---------------- family-safe PTX helpers ----------------
__device__ __forceinline__ uint32_t smem_to_u32(const void* smem_ptr) {
    uint32_t addr;
    asm("{ .reg .u64 tmp; cvta.to.shared.u64 tmp, %1; cvt.u32.u64 %0, tmp; }"
        : "=r"(addr) : "l"(smem_ptr));
    return addr;
}
#define CP_ASYNC16(dst_u32, src_ptr) \
    asm volatile("cp.async.cg.shared.global [%0], [%1], 16;" \
        :: "r"(dst_u32), "l"(src_ptr))
#define CP_COMMIT() asm volatile("cp.async.commit_group;" ::: "memory")
#define CP_WAIT1()  asm volatile("cp.async.wait_group 1;" ::: "memory")
#define CP_WAIT2()  asm volatile("cp.async.wait_group 2;" ::: "memory")

__device__ __forceinline__ void ldsm_x4(uint32_t& r0, uint32_t& r1,
                                        uint32_t& r2, uint32_t& r3, uint32_t addr) {
    asm volatile("ldmatrix.sync.aligned.m8n8.x4.shared.b16 {%0,%1,%2,%3}, [%4];"
        : "=r"(r0), "=r"(r1), "=r"(r2), "=r"(r3) : "r"(addr));
}
__device__ __forceinline__ void mma16816_f16(float* c, const uint32_t* a, const uint32_t* b) {
    asm volatile(
        "mma.sync.aligned.m16n8k16.row.col.f32.f16.f16.f32 "
        "{%0,%1,%2,%3}, {%4,%5,%6,%7}, {%8,%9}, {%0,%1,%2,%3};"
        : "+f"(c[0]), "+f"(c[1]), "+f"(c[2]), "+f"(c[3])
        : "r"(a[0]), "r"(a[1]), "r"(a[2]), "r"(a[3]), "r"(b[0]), "r"(b[1]));
}
__device__ __forceinline__ void mma16816_bf16(float* c, const uint32_t* a, const uint32_t* b) {
    asm volatile(
        "mma.sync.aligned.m16n8k16.row.col.f32.bf16.bf16.f32 "
        "{%0,%1,%2,%3}, {%4,%5,%6,%7}, {%8,%9}, {%0,%1,%2,%3};"
        : "+f"(c[0]), "+f"(c[1]), "+f"(c[2]), "+f"(c[3])
        : "r"(a[0]), "r"(a[1]), "r"(a[2]), "r"(a[3]), "r"(b[0]), "r"(b[1]));
}
#define SWZ128(o) ((o) ^ (((o) >> 3) & 0x70))

// expand 2 spike bits into packed bf16x2 (1.0f / 0.0f halves)
__device__ __forceinline__ uint32_t expand2(uint32_t b) {
    return ((b & 1u) * 0x3F80u) | ((b >> 1) * 0x3F800000u);
}

// ---------------------------------------------------------------------------
// Kernel 0: fused prep. Covers three jobs by linear index range:
//   [0, (M_+H_)*88)        : fp32 -> 2x fp16 split (input rows, then W1 rows)
//   [(M_+H_)*88, +32*1024) : W2 -> 2x bf16 splits (ballot-permuted)
// ---------------------------------------------------------------------------
__global__ void prep_kernel(const float* __restrict__ input,
                            const float* __restrict__ W1,
                            const float* __restrict__ W2,
                            __half* __restrict__ ah, __half* __restrict__ al,
                            __half* __restrict__ wh, __half* __restrict__ wl)
{
    const int GPR = KP_ / 8;  // 88
    const long long total1 = (long long)(M_ + H_) * GPR;
    long long idx = (long long)blockIdx.x * blockDim.x + threadIdx.x;

    if (idx < total1) {
        int mrow = (int)(idx / GPR);
        int g    = (int)(idx % GPR);
        const float* src;
        float scale;
        __half *o0, *o1;
        int row;
        if (mrow < M_) { src = input; scale = A_SCALE; o0 = ah; o1 = al; row = mrow; }
        else           { src = W1;    scale = W_SCALE; o0 = wh; o1 = wl; row = mrow - M_; }

        const float* sp = src + (size_t)row * D_ + g * 8;
        float4 f0 = __ldcs((const float4*)sp);                  // g*8 <= 696 < 700 always
        float4 f1 = (g < GPR - 1) ? __ldcs((const float4*)(sp + 4))
                                  : make_float4(0.f, 0.f, 0.f, 0.f);
        float a[8] = {f0.x * scale, f0.y * scale, f0.z * scale, f0.w * scale,
                      f1.x * scale, f1.y * scale, f1.z * scale, f1.w * scale};
        unsigned short h0[8], h1[8];
#pragma unroll
        for (int i = 0; i < 8; i++) {
            __half hi = __float2half_rn(a[i]);
            __half lo = __float2half_rn(a[i] - __half2float(hi));
            h0[i] = __half_as_ushort(hi);
            h1[i] = __half_as_ushort(lo);
        }
        size_t off = (size_t)row * KP_ + g * 8;
        *(uint4*)(o0 + off) = make_uint4(
            (uint32_t)h0[1] << 16 | h0[0], (uint32_t)h0[3] << 16 | h0[2],
            (uint32_t)h0[5] << 16 | h0[4], (uint32_t)h0[7] << 16 | h0[6]);
        *(uint4*)(o1 + off) = make_uint4(
            (uint32_t)h1[1] << 16 | h1[0], (uint32_t)h1[3] << 16 | h1[2],
            (uint32_t)h1[5] << 16 | h1[4], (uint32_t)h1[7] << 16 | h1[6]);
    } else {
        long long j = idx - total1;
        if (j < 32 * PB_K) {
            int o = (int)(j / PB_K);
            int p = (int)(j % PB_K);
            int w = p >> 5, l = p & 31;
            int h = (w >> 2) * 128 + l * 4 + (w & 3);
            float v = (o < O_) ? W2[o * H_ + h] : 0.0f;
            __nv_bfloat16 hi = __float2bfloat16(v);
            __nv_bfloat16 lo = __float2bfloat16(v - __bfloat162float(hi));
            g_W2s[0][j] = hi;
            g_W2s[1][j] = lo;
        }
    }
}

// ---------------------------------------------------------------------------
// Kernel 1: HMMA fp16 GEMM, fp32 emulation via 3 cross-products.
// R7/R9-proven config, byte-for-byte. FROZEN.
// ---------------------------------------------------------------------------
__global__ __launch_bounds__(256, 2)
void gemm_hmma_kernel(const float* __restrict__ bias)
{
    extern __shared__ __align__(1024) char smem[];
    const uint32_t smem_base = smem_to_u32(smem);
    const int tid  = threadIdx.x;
    const int wid  = tid >> 5;
    const int lane = tid & 31;
    const int wm = wid >> 1;       // 0..3 (m)
    const int wn = wid & 1;        // 0..1 (n)
    const int bm = blockIdx.y * BM;
    const int bn = blockIdx.x * BN;

    uint32_t sdstA[4];
    size_t   goffA[4];
#pragma unroll
    for (int j = 0; j < 4; j++) {
        int c = tid + j * 256;
        int row = c >> 3, unit = c & 7;
        sdstA[j] = SWZ128(row * 128 + unit * 16);
        goffA[j] = (size_t)row * KP_ + unit * 8;
    }
    uint32_t sdstW[2];
    size_t   goffW[2];
#pragma unroll
    for (int j = 0; j < 2; j++) {
        int c = tid + j * 256;
        int row = c >> 3, unit = c & 7;
        sdstW[j] = SWZ128(row * 128 + unit * 16);
        goffW[j] = (size_t)row * KP_ + unit * 8;
    }
    const __half* Asrc[2] = { g_Ah + (size_t)bm * KP_, g_Al + (size_t)bm * KP_ };
    const __half* Wsrc[2] = { g_Wh + (size_t)bn * KP_, g_Wl + (size_t)bn * KP_ };

    const int q  = lane >> 3;
    const int rr = lane & 7;
    uint32_t abyte[2];
#pragma unroll
    for (int mt = 0; mt < 2; mt++) {
        int row = wm * 32 + mt * 16 + (q & 1) * 8 + rr;
        abyte[mt] = (uint32_t)(row * 128 + (q >> 1) * 16);
    }
    uint32_t bbyte[2];
#pragma unroll
    for (int np = 0; np < 2; np++) {
        int row = wn * 32 + np * 16 + (q >> 1) * 8 + rr;
        bbyte[np] = (uint32_t)(row * 128 + (q & 1) * 16);
    }

    float acc[2][4][4];
#pragma unroll
    for (int mt = 0; mt < 2; mt++)
#pragma unroll
        for (int nt = 0; nt < 4; nt++)
#pragma unroll
            for (int i = 0; i < 4; i++) acc[mt][nt][i] = 0.0f;

#define GEMM_LOAD_CHUNK(sb, k0) do { \
    _Pragma("unroll") \
    for (int s = 0; s < 2; s++) { \
        _Pragma("unroll") \
        for (int j = 0; j < 4; j++) \
            CP_ASYNC16((sb) + s * A_TILE_B + sdstA[j], Asrc[s] + goffA[j] + (k0)); \
        _Pragma("unroll") \
        for (int j = 0; j < 2; j++) \
            CP_ASYNC16((sb) + 2 * A_TILE_B + s * W_TILE_B + sdstW[j], \
                       Wsrc[s] + goffW[j] + (k0)); \
    } \
} while (0)

    GEMM_LOAD_CHUNK(smem_base, 0);
    CP_COMMIT();
    GEMM_LOAD_CHUNK(smem_base + STAGE_B, BK);
    CP_COMMIT();

    const int pa[3] = {0, 0, 1};
    const int pb[3] = {0, 1, 0};

    for (int k = 0; k < NCHUNK; k++) {
        CP_WAIT1();
        __syncthreads();

        const uint32_t stage = smem_base + (k & 1) * STAGE_B;
#pragma unroll
        for (int kk = 0; kk < 4; kk++) {
            uint32_t af[2][2][4];
            uint32_t bf[2][4][2];
#pragma unroll
            for (int s = 0; s < 2; s++) {
#pragma unroll
                for (int mt = 0; mt < 2; mt++)
                    ldsm_x4(af[s][mt][0], af[s][mt][1], af[s][mt][2], af[s][mt][3],
                            stage + s * A_TILE_B + SWZ128(abyte[mt] + kk * 32));
#pragma unroll
                for (int np = 0; np < 2; np++)
                    ldsm_x4(bf[s][np * 2][0], bf[s][np * 2][1],
                            bf[s][np * 2 + 1][0], bf[s][np * 2 + 1][1],
                            stage + 2 * A_TILE_B + s * W_TILE_B
                                  + SWZ128(bbyte[np] + kk * 32));
            }
#pragma unroll
            for (int p = 0; p < 3; p++)
#pragma unroll
                for (int mt = 0; mt < 2; mt++)
#pragma unroll
                    for (int nt = 0; nt < 4; nt++)
                        mma16816_f16(acc[mt][nt], af[pa[p]][mt], bf[pb[p]][nt]);
        }
        __syncthreads();

        if (k + NSTAGE < NCHUNK) {
            GEMM_LOAD_CHUNK(smem_base + (k & 1) * STAGE_B, (k + NSTAGE) * BK);
        }
        CP_COMMIT();
    }

    const int mrow0 = bm + wm * 32;
    const int ncol0 = bn + wn * 32;
    const int lr = lane >> 2;
    const int lc = (lane & 3) * 2;
#pragma unroll
    for (int mt = 0; mt < 2; mt++) {
#pragma unroll
        for (int nt = 0; nt < 4; nt++) {
            int r = mrow0 + mt * 16 + lr;
            int c = ncol0 + nt * 8 + lc;
            float bx = __ldg(bias + c), by = __ldg(bias + c + 1);
            float2 v0 = make_float2(acc[mt][nt][0] * INV_SCALE + bx,
                                    acc[mt][nt][1] * INV_SCALE + by);
            float2 v1 = make_float2(acc[mt][nt][2] * INV_SCALE + bx,
                                    acc[mt][nt][3] * INV_SCALE + by);
            *(float2*)(g_d1 + (size_t)r * H_ + c)       = v0;
            *(float2*)(g_d1 + (size_t)(r + 8) * H_ + c) = v1;
        }
    }
}

// ---------------------------------------------------------------------------
// Kernel 2a: LIF layer-1 chains -> spike BITMASKS via ballot. 512 CTAs x 128.
// R12-proven: 4-deep register prefetch ring + __ldcs streaming loads.
// word w = gwarp*4 + j holds at bit l the spike of h = gwarp*128 + l*4 + j.
// ---------------------------------------------------------------------------
__global__ __launch_bounds__(128) void lif1_kernel(
    const float* __restrict__ d1,
    const float* __restrict__ tau1)
{
    const int b    = blockIdx.x >> 1;
    const int half = blockIdx.x & 1;
    const int tid  = threadIdx.x;
    const int wl   = tid >> 5;
    const int lane = tid & 31;
    const int h0   = half * 512 + tid * 4;

    float4 tv = *(const float4*)(tau1 + h0);
    float a1[4], om[4], mem[4], spk[4];
    a1[0] = 1.0f / (1.0f + expf(-tv.x));
    a1[1] = 1.0f / (1.0f + expf(-tv.y));
    a1[2] = 1.0f / (1.0f + expf(-tv.z));
    a1[3] = 1.0f / (1.0f + expf(-tv.w));
#pragma unroll
    for (int j = 0; j < 4; j++) { om[j] = 1.0f - a1[j]; mem[j] = 0.0f; spk[j] = 0.0f; }

    const float* dp = d1 + (size_t)b * T_ * H_ + h0;
    uint32_t* mp = g_msk + (size_t)b * T_ * 32 + (half * 4 + wl) * 4;

    float4 pre[4];
#pragma unroll
    for (int i = 0; i < 4; i++)
        pre[i] = __ldcs((const float4*)(dp + (size_t)i * H_));

#pragma unroll 4
    for (int t = 0; t < T_; t++) {
        float4 c = pre[t & 3];
        if (t + 4 < T_)
            pre[t & 3] = __ldcs((const float4*)(dp + (size_t)(t + 4) * H_));
        float cur[4] = {c.x, c.y, c.z, c.w};

#pragma unroll
        for (int j = 0; j < 4; j++) {
            mem[j] = mem[j] * a1[j] + om[j] * cur[j] - spk[j];
            spk[j] = (mem[j] > 1.0f) ? 1.0f : 0.0f;
        }
        uint32_t bits0 = __ballot_sync(0xffffffffu, mem[0] > 1.0f);
        uint32_t bits1 = __ballot_sync(0xffffffffu, mem[1] > 1.0f);
        uint32_t bits2 = __ballot_sync(0xffffffffu, mem[2] > 1.0f);
        uint32_t bits3 = __ballot_sync(0xffffffffu, mem[3] > 1.0f);
        if (lane < 4) {
            uint32_t w = (lane == 0) ? bits0 : (lane == 1) ? bits1
                       : (lane == 2) ? bits2 : bits3;
            mp[(size_t)t * 32 + lane] = w;
        }
    }
}

// ---------------------------------------------------------------------------
// Kernel 2b: d2^T = W2splits[32,1024] @ spk^T. Bitmask-expanded spikes.
// R9-proven: PB_ROWS=256 -> 250 CTAs, 96KB smem, W2 in race-free 4-deep ring.
// ---------------------------------------------------------------------------
__global__ __launch_bounds__(256, 2)
void d2_gemm_kernel()
{
    extern __shared__ __align__(1024) char smem[];
    const uint32_t smem_base = smem_to_u32(smem);
    const int tid  = threadIdx.x;
    const int wid  = tid >> 5;
    const int lane = tid & 31;
    const int m0 = blockIdx.x * PB_ROWS;

    uint32_t ebase[2];
    const uint32_t* mrow[2];
#pragma unroll
    for (int i = 0; i < 2; i++) {
        int idx = tid + i * 256;
        int r = idx >> 1, wq = idx & 1;
        ebase[i] = (uint32_t)(r * 128 + wq * 64);
        mrow[i]  = g_msk + (size_t)(m0 + r) * 32 + wq;
    }

    const int wrow = tid >> 3, wunit = tid & 7;
    const uint32_t w_sdst = SWZ128(wrow * 128 + wunit * 16);
    const size_t   w_goff = (size_t)wrow * PB_K + wunit * 8;
    const uint32_t w2smem = smem_base + 2 * PB_SPKBUF;

    const int q  = lane >> 3;
    const int rr = lane & 7;
    uint32_t abyte[2];
#pragma unroll
    for (int mt = 0; mt < 2; mt++) {
        int row = mt * 16 + (q & 1) * 8 + rr;
        abyte[mt] = (uint32_t)(row * 128 + (q >> 1) * 16);
    }
    uint32_t bbyte[2];
#pragma unroll
    for (int np = 0; np < 2; np++) {
        int row = wid * 32 + np * 16 + (q >> 1) * 8 + rr;
        bbyte[np] = (uint32_t)(row * 128 + (q & 1) * 16);
    }

    float acc[2][4][4];
#pragma unroll
    for (int mt = 0; mt < 2; mt++)
#pragma unroll
        for (int nt = 0; nt < 4; nt++)
#pragma unroll
            for (int i = 0; i < 4; i++) acc[mt][nt][i] = 0.0f;

#pragma unroll
    for (int pk = 0; pk < 2; pk++) {
#pragma unroll
        for (int p = 0; p < 2; p++)
            CP_ASYNC16(w2smem + pk * PB_W2STAGE + p * PB_W2TILE + w_sdst,
                       &g_W2s[p][0] + w_goff + pk * PB_BK);
        CP_COMMIT();
    }
    uint32_t mcur[2];
#pragma unroll
    for (int i = 0; i < 2; i++) mcur[i] = mrow[i][0];

    for (int kc = 0; kc < PB_NCH; kc++) {
        __syncthreads();

        if (kc + 2 < PB_NCH) {
#pragma unroll
            for (int p = 0; p < 2; p++)
                CP_ASYNC16(w2smem + ((kc + 2) & 3) * PB_W2STAGE + p * PB_W2TILE + w_sdst,
                           &g_W2s[p][0] + w_goff + (kc + 2) * PB_BK);
        }
        CP_COMMIT();

        char* sb = smem + (kc & 1) * PB_SPKBUF;
#pragma unroll
        for (int i = 0; i < 2; i++) {
            uint32_t W = mcur[i];
#pragma unroll
            for (int g = 0; g < 4; g++) {
                uint4 u;
                u.x = expand2((W >> (g * 8 + 0)) & 3u);
                u.y = expand2((W >> (g * 8 + 2)) & 3u);
                u.z = expand2((W >> (g * 8 + 4)) & 3u);
                u.w = expand2((W >> (g * 8 + 6)) & 3u);
                *(uint4*)(sb + SWZ128(ebase[i] + g * 16)) = u;
            }
        }
        CP_WAIT2();
        __syncthreads();

        const uint32_t spkb = smem_base + (kc & 1) * PB_SPKBUF;
        const uint32_t w2b  = w2smem + (kc & 3) * PB_W2STAGE;
#pragma unroll
        for (int kk = 0; kk < 4; kk++) {
            uint32_t bf[4][2];
#pragma unroll
            for (int np = 0; np < 2; np++)
                ldsm_x4(bf[np * 2][0], bf[np * 2][1], bf[np * 2 + 1][0], bf[np * 2 + 1][1],
                        spkb + SWZ128(bbyte[np] + kk * 32));
#pragma unroll
            for (int p = 0; p < 2; p++) {
                uint32_t af[2][4];
#pragma unroll
                for (int mt = 0; mt < 2; mt++)
                    ldsm_x4(af[mt][0], af[mt][1], af[mt][2], af[mt][3],
                            w2b + p * PB_W2TILE + SWZ128(abyte[mt] + kk * 32));
#pragma unroll
                for (int mt = 0; mt < 2; mt++)
#pragma unroll
                    for (int nt = 0; nt < 4; nt++)
                        mma16816_bf16(acc[mt][nt], af[mt], bf[nt]);
            }
        }

        if (kc + 1 < PB_NCH) {
#pragma unroll
            for (int i = 0; i < 2; i++) mcur[i] = mrow[i][(kc + 1) * 2];
        }
    }

#pragma unroll
    for (int mt = 0; mt < 2; mt++) {
#pragma unroll
        for (int nt = 0; nt < 4; nt++) {
            int o  = mt * 16 + (lane >> 2);
            int n  = wid * 32 + nt * 8 + (lane & 3) * 2;
            size_t gm = (size_t)(m0 + n);
            g_d2[gm * 32 + o]           = acc[mt][nt][0];
            g_d2[(gm + 1) * 32 + o]     = acc[mt][nt][1];
            g_d2[gm * 32 + o + 8]       = acc[mt][nt][2];
            g_d2[(gm + 1) * 32 + o + 8] = acc[mt][nt][3];
        }
    }
}

// ---------------------------------------------------------------------------
// Kernel 2c: readout EMA + softmax accumulate, SHFL-FREE via smem transpose.
// Chunks of 32 timesteps: pass1 lane-o computes e(t,o) into smem; pass2
// lane-t serially sums 20 values -> 1/s; pass3 lane-o accumulates e*rs.
// Max-free exp is safe (|mem2| << 88).
// ---------------------------------------------------------------------------
__global__ __launch_bounds__(256) void readout_kernel(
    const float* __restrict__ tau2,
    const float* __restrict__ b2,
    float* __restrict__ out)
{
    __shared__ float e_buf[8][32][21];   // [warp][tt][o], padded row 21
    __shared__ float rs_buf[8][32];

    const int warp = threadIdx.x >> 5;
    const int lane = threadIdx.x & 31;
    const int b = blockIdx.x * 8 + warp;

    float a2 = 0.0f, oma2 = 0.0f, bb = 0.0f, mem2 = 0.0f, accv = 0.0f;
    if (lane < O_) {
        a2 = 1.0f / (1.0f + expf(-tau2[lane]));
        oma2 = 1.0f - a2;
        bb = b2[lane];
    }

    const float* dp = g_d2 + (size_t)b * T_ * 32;
    float pre[4];
#pragma unroll
    for (int i = 0; i < 4; i++)
        pre[i] = dp[(size_t)i * 32 + lane];

    int t = 0;
    for (int c = 0; c < 8; c++) {
        const int len = (c == 7) ? (T_ - 7 * 32) : 32;   // 26 for last chunk

        // pass 1: per-lane-o EMA + exp -> smem
        for (int tt = 0; tt < len; tt++, t++) {
            float v = pre[t & 3];
            if (t + 4 < T_) pre[t & 3] = dp[(size_t)(t + 4) * 32 + lane];
            if (lane < O_) {
                mem2 = mem2 * a2 + oma2 * (v + bb);
                e_buf[warp][tt][lane] = expf(mem2);
            }
        }
        __syncwarp();

        // pass 2: per-lane-t serial sum over o, store reciprocal
        if (lane < len) {
            float s0 = 0.0f, s1 = 0.0f;
#pragma unroll
            for (int o = 0; o < O_; o += 2) {
                s0 += e_buf[warp][lane][o];
                s1 += e_buf[warp][lane][o + 1];
            }
            rs_buf[warp][lane] = 1.0f / (s0 + s1);
        }
        __syncwarp();

        // pass 3: per-lane-o accumulate e * rs over the chunk (t > 10 gate)
        if (lane < O_) {
            const int tbase = c * 32;
            for (int tt = 0; tt < len; tt++) {
                if (tbase + tt > 10)
                    accv += e_buf[warp][tt][lane] * rs_buf[warp][tt];
            }
        }
        __syncwarp();   // protect e_buf/rs_buf before next chunk's pass 1
    }

    if (lane < O_) out[b * O_ + lane] = accv;
}

// ---------------------------------------------------------------------------
extern "C" void kernel_launch(void* const* d_in, const int* in_sizes, int n_in,
                              void* d_out, int out_size)
{
    const float* input = (const float*)d_in[0];  // [B,T,D]
    const float* W1    = (const float*)d_in[1];  // [H,D]
    const float* b1    = (const float*)d_in[2];  // [H]
    const float* tau1  = (const float*)d_in[3];  // [H]
    const float* W2    = (const float*)d_in[4];  // [O,H]
    const float* b2    = (const float*)d_in[5];  // [O]
    const float* tau2  = (const float*)d_in[6];  // [O]
    float* out = (float*)d_out;                  // [B,O]

    cudaFuncSetAttribute(gemm_hmma_kernel,
                         cudaFuncAttributeMaxDynamicSharedMemorySize, SMEM_TOTAL);
    cudaFuncSetAttribute(d2_gemm_kernel,
                         cudaFuncAttributeMaxDynamicSharedMemorySize, PB_SMEM);

    __half *ah, *al, *wh, *wl;
    float *d1p;
    cudaGetSymbolAddress((void**)&ah,  g_Ah);
    cudaGetSymbolAddress((void**)&al,  g_Al);
    cudaGetSymbolAddress((void**)&wh,  g_Wh);
    cudaGetSymbolAddress((void**)&wl,  g_Wl);
    cudaGetSymbolAddress((void**)&d1p, g_d1);

    {
        long long total = (long long)(M_ + H_) * (KP_ / 8) + 32LL * PB_K;
        int blocks = (int)((total + 255) / 256);
        prep_kernel<<<blocks, 256>>>(input, W1, W2, ah, al, wh, wl);
    }

    dim3 ggrid(H_ / BN, M_ / BM);  // (16, 500) = 8000 CTAs
    gemm_hmma_kernel<<<ggrid, 256, SMEM_TOTAL>>>(b1);

    lif1_kernel<<<2 * B_, 128>>>(d1p, tau1);
    d2_gemm_kernel<<<M_ / PB_ROWS, 256, PB_SMEM>>>();   // 250 CTAs
    readout_kernel<<<B_ / 8, 256>>>(tau2, b2, out);
}

// round 14
// speedup vs baseline: 1.1344x; 1.0118x over previous
#include <cuda_runtime.h>
#include <cuda_fp16.h>
#include <cuda_bf16.h>
#include <math_constants.h>
#include <cstdint>

// ---------------- shapes ----------------
#define B_  256
#define T_  250
#define D_  700
#define H_  1024
#define O_  20
#define M_  (B_ * T_)   // 64000
#define KP_ 704         // K padded to multiple of 64

// ---------------- main GEMM tiling (R7/R9-proven config; FROZEN) ----------------
#define BM 128
#define BN 64
#define BK 64
#define NCHUNK (KP_ / BK)              // 11
#define A_TILE_B (BM * BK * 2)         // 16384
#define W_TILE_B (BN * BK * 2)         // 8192
#define STAGE_B (2 * A_TILE_B + 2 * W_TILE_B)  // 49152
#define NSTAGE 2
#define SMEM_TOTAL (NSTAGE * STAGE_B)  // 98304 -> 2 CTAs/SM

#define A_SCALE 2048.0f
#define W_SCALE 64.0f
#define INV_SCALE (1.0f / (A_SCALE * W_SCALE))   // 2^-17, exact

// ---------------- phase-B (d2) GEMM tiling ----------------
#define PB_ROWS 256
#define PB_K    1024
#define PB_BK   64
#define PB_NCH  (PB_K / PB_BK)             // 16
#define PB_SPKBUF  (PB_ROWS * PB_BK * 2)   // 32768 per buffer
#define PB_W2TILE  (32 * PB_BK * 2)        // 4096 per split
#define PB_W2STAGE (2 * PB_W2TILE)         // 8192
#define PB_W2RING  4
#define PB_LUT_OFF (2 * PB_SPKBUF + PB_W2RING * PB_W2STAGE)  // 98304
#define PB_SMEM (PB_LUT_OFF + 4096)        // 102400 (<= 114KB for 2 CTAs/SM)

// ---------------- scratch (static device globals; no allocation) ----------------
__device__ float g_d1[(size_t)M_ * H_];
__device__ __half g_Ah[(size_t)M_ * KP_];
__device__ __half g_Al[(size_t)M_ * KP_];
__device__ __half g_Wh[(size_t)H_ * KP_];
__device__ __half g_Wl[(size_t)H_ * KP_];
__device__ uint32_t g_msk[(size_t)M_ * 32];            // spike bitmasks
__device__ __nv_bfloat16 g_W2s[2][32 * PB_K];          // W2 hi/lo bf16 splits (bit-permuted)
__device__ float g_d2[(size_t)M_ * 32];                // d2 (padded to 32 outputs)

// ---------------- family-safe PTX helpers ----------------
__device__ __forceinline__ uint32_t smem_to_u32(const void* smem_ptr) {
    uint32_t addr;
    asm("{ .reg .u64 tmp; cvta.to.shared.u64 tmp, %1; cvt.u32.u64 %0, tmp; }"
        : "=r"(addr) : "l"(smem_ptr));
    return addr;
}
#define CP_ASYNC16(dst_u32, src_ptr) \
    asm volatile("cp.async.cg.shared.global [%0], [%1], 16;" \
        :: "r"(dst_u32), "l"(src_ptr))
#define CP_COMMIT() asm volatile("cp.async.commit_group;" ::: "memory")
#define CP_WAIT1()  asm volatile("cp.async.wait_group 1;" ::: "memory")
#define CP_WAIT2()  asm volatile("cp.async.wait_group 2;" ::: "memory")

__device__ __forceinline__ void ldsm_x4(uint32_t& r0, uint32_t& r1,
                                        uint32_t& r2, uint32_t& r3, uint32_t addr) {
    asm volatile("ldmatrix.sync.aligned.m8n8.x4.shared.b16 {%0,%1,%2,%3}, [%4];"
        : "=r"(r0), "=r"(r1), "=r"(r2), "=r"(r3) : "r"(addr));
}
__device__ __forceinline__ void mma16816_f16(float* c, const uint32_t* a, const uint32_t* b) {
    asm volatile(
        "mma.sync.aligned.m16n8k16.row.col.f32.f16.f16.f32 "
        "{%0,%1,%2,%3}, {%4,%5,%6,%7}, {%8,%9}, {%0,%1,%2,%3};"
        : "+f"(c[0]), "+f"(c[1]), "+f"(c[2]), "+f"(c[3])
        : "r"(a[0]), "r"(a[1]), "r"(a[2]), "r"(a[3]), "r"(b[0]), "r"(b[1]));
}
__device__ __forceinline__ void mma16816_bf16(float* c, const uint32_t* a, const uint32_t* b) {
    asm volatile(
        "mma.sync.aligned.m16n8k16.row.col.f32.bf16.bf16.f32 "
        "{%0,%1,%2,%3}, {%4,%5,%6,%7}, {%8,%9}, {%0,%1,%2,%3};"
        : "+f"(c[0]), "+f"(c[1]), "+f"(c[2]), "+f"(c[3])
        : "r"(a[0]), "r"(a[1]), "r"(a[2]), "r"(a[3]), "r"(b[0]), "r"(b[1]));
}
#define SWZ128(o) ((o) ^ (((o) >> 3) & 0x70))

// expand 2 spike bits into packed bf16x2 (1.0f / 0.0f halves)
__device__ __forceinline__ uint32_t expand2(uint32_t b) {
    return ((b & 1u) * 0x3F80u) | ((b >> 1) * 0x3F800000u);
}

// ---------------------------------------------------------------------------
// Kernel 0: fused prep (R13-proven).
// ---------------------------------------------------------------------------
__global__ void prep_kernel(const float* __restrict__ input,
                            const float* __restrict__ W1,
                            const float* __restrict__ W2,
                            __half* __restrict__ ah, __half* __restrict__ al,
                            __half* __restrict__ wh, __half* __restrict__ wl)
{
    const int GPR = KP_ / 8;  // 88
    const long long total1 = (long long)(M_ + H_) * GPR;
    long long idx = (long long)blockIdx.x * blockDim.x + threadIdx.x;

    if (idx < total1) {
        int mrow = (int)(idx / GPR);
        int g    = (int)(idx % GPR);
        const float* src;
        float scale;
        __half *o0, *o1;
        int row;
        if (mrow < M_) { src = input; scale = A_SCALE; o0 = ah; o1 = al; row = mrow; }
        else           { src = W1;    scale = W_SCALE; o0 = wh; o1 = wl; row = mrow - M_; }

        const float* sp = src + (size_t)row * D_ + g * 8;
        float4 f0 = __ldcs((const float4*)sp);
        float4 f1 = (g < GPR - 1) ? __ldcs((const float4*)(sp + 4))
                                  : make_float4(0.f, 0.f, 0.f, 0.f);
        float a[8] = {f0.x * scale, f0.y * scale, f0.z * scale, f0.w * scale,
                      f1.x * scale, f1.y * scale, f1.z * scale, f1.w * scale};
        unsigned short h0[8], h1[8];
#pragma unroll
        for (int i = 0; i < 8; i++) {
            __half hi = __float2half_rn(a[i]);
            __half lo = __float2half_rn(a[i] - __half2float(hi));
            h0[i] = __half_as_ushort(hi);
            h1[i] = __half_as_ushort(lo);
        }
        size_t off = (size_t)row * KP_ + g * 8;
        *(uint4*)(o0 + off) = make_uint4(
            (uint32_t)h0[1] << 16 | h0[0], (uint32_t)h0[3] << 16 | h0[2],
            (uint32_t)h0[5] << 16 | h0[4], (uint32_t)h0[7] << 16 | h0[6]);
        *(uint4*)(o1 + off) = make_uint4(
            (uint32_t)h1[1] << 16 | h1[0], (uint32_t)h1[3] << 16 | h1[2],
            (uint32_t)h1[5] << 16 | h1[4], (uint32_t)h1[7] << 16 | h1[6]);
    } else {
        long long j = idx - total1;
        if (j < 32 * PB_K) {
            int o = (int)(j / PB_K);
            int p = (int)(j % PB_K);
            int w = p >> 5, l = p & 31;
            int h = (w >> 2) * 128 + l * 4 + (w & 3);
            float v = (o < O_) ? W2[o * H_ + h] : 0.0f;
            __nv_bfloat16 hi = __float2bfloat16(v);
            __nv_bfloat16 lo = __float2bfloat16(v - __bfloat162float(hi));
            g_W2s[0][j] = hi;
            g_W2s[1][j] = lo;
        }
    }
}

// ---------------------------------------------------------------------------
// Kernel 1: HMMA fp16 GEMM (FROZEN, R7/R9 byte-for-byte).
// ---------------------------------------------------------------------------
__global__ __launch_bounds__(256, 2)
void gemm_hmma_kernel(const float* __restrict__ bias)
{
    extern __shared__ __align__(1024) char smem[];
    const uint32_t smem_base = smem_to_u32(smem);
    const int tid  = threadIdx.x;
    const int wid  = tid >> 5;
    const int lane = tid & 31;
    const int wm = wid >> 1;
    const int wn = wid & 1;
    const int bm = blockIdx.y * BM;
    const int bn = blockIdx.x * BN;

    uint32_t sdstA[4];
    size_t   goffA[4];
#pragma unroll
    for (int j = 0; j < 4; j++) {
        int c = tid + j * 256;
        int row = c >> 3, unit = c & 7;
        sdstA[j] = SWZ128(row * 128 + unit * 16);
        goffA[j] = (size_t)row * KP_ + unit * 8;
    }
    uint32_t sdstW[2];
    size_t   goffW[2];
#pragma unroll
    for (int j = 0; j < 2; j++) {
        int c = tid + j * 256;
        int row = c >> 3, unit = c & 7;
        sdstW[j] = SWZ128(row * 128 + unit * 16);
        goffW[j] = (size_t)row * KP_ + unit * 8;
    }
    const __half* Asrc[2] = { g_Ah + (size_t)bm * KP_, g_Al + (size_t)bm * KP_ };
    const __half* Wsrc[2] = { g_Wh + (size_t)bn * KP_, g_Wl + (size_t)bn * KP_ };

    const int q  = lane >> 3;
    const int rr = lane & 7;
    uint32_t abyte[2];
#pragma unroll
    for (int mt = 0; mt < 2; mt++) {
        int row = wm * 32 + mt * 16 + (q & 1) * 8 + rr;
        abyte[mt] = (uint32_t)(row * 128 + (q >> 1) * 16);
    }
    uint32_t bbyte[2];
#pragma unroll
    for (int np = 0; np < 2; np++) {
        int row = wn * 32 + np * 16 + (q >> 1) * 8 + rr;
        bbyte[np] = (uint32_t)(row * 128 + (q & 1) * 16);
    }

    float acc[2][4][4];
#pragma unroll
    for (int mt = 0; mt < 2; mt++)
#pragma unroll
        for (int nt = 0; nt < 4; nt++)
#pragma unroll
            for (int i = 0; i < 4; i++) acc[mt][nt][i] = 0.0f;

#define GEMM_LOAD_CHUNK(sb, k0) do { \
    _Pragma("unroll") \
    for (int s = 0; s < 2; s++) { \
        _Pragma("unroll") \
        for (int j = 0; j < 4; j++) \
            CP_ASYNC16((sb) + s * A_TILE_B + sdstA[j], Asrc[s] + goffA[j] + (k0)); \
        _Pragma("unroll") \
        for (int j = 0; j < 2; j++) \
            CP_ASYNC16((sb) + 2 * A_TILE_B + s * W_TILE_B + sdstW[j], \
                       Wsrc[s] + goffW[j] + (k0)); \
    } \
} while (0)

    GEMM_LOAD_CHUNK(smem_base, 0);
    CP_COMMIT();
    GEMM_LOAD_CHUNK(smem_base + STAGE_B, BK);
    CP_COMMIT();

    const int pa[3] = {0, 0, 1};
    const int pb[3] = {0, 1, 0};

    for (int k = 0; k < NCHUNK; k++) {
        CP_WAIT1();
        __syncthreads();

        const uint32_t stage = smem_base + (k & 1) * STAGE_B;
#pragma unroll
        for (int kk = 0; kk < 4; kk++) {
            uint32_t af[2][2][4];
            uint32_t bf[2][4][2];
#pragma unroll
            for (int s = 0; s < 2; s++) {
#pragma unroll
                for (int mt = 0; mt < 2; mt++)
                    ldsm_x4(af[s][mt][0], af[s][mt][1], af[s][mt][2], af[s][mt][3],
                            stage + s * A_TILE_B + SWZ128(abyte[mt] + kk * 32));
#pragma unroll
                for (int np = 0; np < 2; np++)
                    ldsm_x4(bf[s][np * 2][0], bf[s][np * 2][1],
                            bf[s][np * 2 + 1][0], bf[s][np * 2 + 1][1],
                            stage + 2 * A_TILE_B + s * W_TILE_B
                                  + SWZ128(bbyte[np] + kk * 32));
            }
#pragma unroll
            for (int p = 0; p < 3; p++)
#pragma unroll
                for (int mt = 0; mt < 2; mt++)
#pragma unroll
                    for (int nt = 0; nt < 4; nt++)
                        mma16816_f16(acc[mt][nt], af[pa[p]][mt], bf[pb[p]][nt]);
        }
        __syncthreads();

        if (k + NSTAGE < NCHUNK) {
            GEMM_LOAD_CHUNK(smem_base + (k & 1) * STAGE_B, (k + NSTAGE) * BK);
        }
        CP_COMMIT();
    }

    const int mrow0 = bm + wm * 32;
    const int ncol0 = bn + wn * 32;
    const int lr = lane >> 2;
    const int lc = (lane & 3) * 2;
#pragma unroll
    for (int mt = 0; mt < 2; mt++) {
#pragma unroll
        for (int nt = 0; nt < 4; nt++) {
            int r = mrow0 + mt * 16 + lr;
            int c = ncol0 + nt * 8 + lc;
            float bx = __ldg(bias + c), by = __ldg(bias + c + 1);
            float2 v0 = make_float2(acc[mt][nt][0] * INV_SCALE + bx,
                                    acc[mt][nt][1] * INV_SCALE + by);
            float2 v1 = make_float2(acc[mt][nt][2] * INV_SCALE + bx,
                                    acc[mt][nt][3] * INV_SCALE + by);
            *(float2*)(g_d1 + (size_t)r * H_ + c)       = v0;
            *(float2*)(g_d1 + (size_t)(r + 8) * H_ + c) = v1;
        }
    }
}

// ---------------------------------------------------------------------------
// Kernel 2a: LIF layer-1 chains -> spike BITMASKS via ballot. 512 CTAs x 128.
// 8-deep register prefetch ring + __ldcs streaming loads.
// ---------------------------------------------------------------------------
__global__ __launch_bounds__(128) void lif1_kernel(
    const float* __restrict__ d1,
    const float* __restrict__ tau1)
{
    const int b    = blockIdx.x >> 1;
    const int half = blockIdx.x & 1;
    const int tid  = threadIdx.x;
    const int wl   = tid >> 5;
    const int lane = tid & 31;
    const int h0   = half * 512 + tid * 4;

    float4 tv = *(const float4*)(tau1 + h0);
    float a1[4], om[4], mem[4], spk[4];
    a1[0] = 1.0f / (1.0f + expf(-tv.x));
    a1[1] = 1.0f / (1.0f + expf(-tv.y));
    a1[2] = 1.0f / (1.0f + expf(-tv.z));
    a1[3] = 1.0f / (1.0f + expf(-tv.w));
#pragma unroll
    for (int j = 0; j < 4; j++) { om[j] = 1.0f - a1[j]; mem[j] = 0.0f; spk[j] = 0.0f; }

    const float* dp = d1 + (size_t)b * T_ * H_ + h0;
    uint32_t* mp = g_msk + (size_t)b * T_ * 32 + (half * 4 + wl) * 4;

    // 8-deep prefetch ring
    float4 pre[8];
#pragma unroll
    for (int i = 0; i < 8; i++)
        pre[i] = __ldcs((const float4*)(dp + (size_t)i * H_));

#pragma unroll 8
    for (int t = 0; t < T_; t++) {
        float4 c = pre[t & 7];
        if (t + 8 < T_)
            pre[t & 7] = __ldcs((const float4*)(dp + (size_t)(t + 8) * H_));
        float cur[4] = {c.x, c.y, c.z, c.w};

#pragma unroll
        for (int j = 0; j < 4; j++) {
            mem[j] = mem[j] * a1[j] + om[j] * cur[j] - spk[j];
            spk[j] = (mem[j] > 1.0f) ? 1.0f : 0.0f;
        }
        uint32_t bits0 = __ballot_sync(0xffffffffu, mem[0] > 1.0f);
        uint32_t bits1 = __ballot_sync(0xffffffffu, mem[1] > 1.0f);
        uint32_t bits2 = __ballot_sync(0xffffffffu, mem[2] > 1.0f);
        uint32_t bits3 = __ballot_sync(0xffffffffu, mem[3] > 1.0f);
        if (lane < 4) {
            uint32_t w = (lane == 0) ? bits0 : (lane == 1) ? bits1
                       : (lane == 2) ? bits2 : bits3;
            mp[(size_t)t * 32 + lane] = w;
        }
    }
}

// ---------------------------------------------------------------------------
// Kernel 2b: d2^T = W2splits[32,1024] @ spk^T. Bitmask-expanded spikes via
// smem LUT (byte -> uint4 of 8 packed bf16; bit-identical to expand2 path).
// W2 in race-free 4-deep ring. PB_ROWS=256 -> 250 CTAs, 100KB smem, 2/SM.
// ---------------------------------------------------------------------------
__global__ __launch_bounds__(256, 2)
void d2_gemm_kernel()
{
    extern __shared__ __align__(1024) char smem[];
    const uint32_t smem_base = smem_to_u32(smem);
    uint4* lut = (uint4*)(smem + PB_LUT_OFF);
    const int tid  = threadIdx.x;
    const int wid  = tid >> 5;
    const int lane = tid & 31;
    const int m0 = blockIdx.x * PB_ROWS;

    // build LUT (256 entries, one per thread); visible after first loop barrier
    {
        uint32_t v = (uint32_t)tid;
        uint4 u;
        u.x = expand2(v & 3u);
        u.y = expand2((v >> 2) & 3u);
        u.z = expand2((v >> 4) & 3u);
        u.w = expand2((v >> 6) & 3u);
        lut[tid] = u;
    }

    uint32_t ebase[2];
    const uint32_t* mrow[2];
#pragma unroll
    for (int i = 0; i < 2; i++) {
        int idx = tid + i * 256;
        int r = idx >> 1, wq = idx & 1;
        ebase[i] = (uint32_t)(r * 128 + wq * 64);
        mrow[i]  = g_msk + (size_t)(m0 + r) * 32 + wq;
    }

    const int wrow = tid >> 3, wunit = tid & 7;
    const uint32_t w_sdst = SWZ128(wrow * 128 + wunit * 16);
    const size_t   w_goff = (size_t)wrow * PB_K + wunit * 8;
    const uint32_t w2smem = smem_base + 2 * PB_SPKBUF;

    const int q  = lane >> 3;
    const int rr = lane & 7;
    uint32_t abyte[2];
#pragma unroll
    for (int mt = 0; mt < 2; mt++) {
        int row = mt * 16 + (q & 1) * 8 + rr;
        abyte[mt] = (uint32_t)(row * 128 + (q >> 1) * 16);
    }
    uint32_t bbyte[2];
#pragma unroll
    for (int np = 0; np < 2; np++) {
        int row = wid * 32 + np * 16 + (q >> 1) * 8 + rr;
        bbyte[np] = (uint32_t)(row * 128 + (q & 1) * 16);
    }

    float acc[2][4][4];
#pragma unroll
    for (int mt = 0; mt < 2; mt++)
#pragma unroll
        for (int nt = 0; nt < 4; nt++)
#pragma unroll
            for (int i = 0; i < 4; i++) acc[mt][nt][i] = 0.0f;

#pragma unroll
    for (int pk = 0; pk < 2; pk++) {
#pragma unroll
        for (int p = 0; p < 2; p++)
            CP_ASYNC16(w2smem + pk * PB_W2STAGE + p * PB_W2TILE + w_sdst,
                       &g_W2s[p][0] + w_goff + pk * PB_BK);
        CP_COMMIT();
    }
    uint32_t mcur[2];
#pragma unroll
    for (int i = 0; i < 2; i++) mcur[i] = mrow[i][0];

    for (int kc = 0; kc < PB_NCH; kc++) {
        __syncthreads();   // LUT (kc=0) + spkbuf/ring reuse safety

        if (kc + 2 < PB_NCH) {
#pragma unroll
            for (int p = 0; p < 2; p++)
                CP_ASYNC16(w2smem + ((kc + 2) & 3) * PB_W2STAGE + p * PB_W2TILE + w_sdst,
                           &g_W2s[p][0] + w_goff + (kc + 2) * PB_BK);
        }
        CP_COMMIT();

        // expand masks -> spk bf16 tile via LUT
        char* sb = smem + (kc & 1) * PB_SPKBUF;
#pragma unroll
        for (int i = 0; i < 2; i++) {
            uint32_t W = mcur[i];
#pragma unroll
            for (int g = 0; g < 4; g++) {
                *(uint4*)(sb + SWZ128(ebase[i] + g * 16)) = lut[(W >> (g * 8)) & 0xFFu];
            }
        }
        CP_WAIT2();
        __syncthreads();

        const uint32_t spkb = smem_base + (kc & 1) * PB_SPKBUF;
        const uint32_t w2b  = w2smem + (kc & 3) * PB_W2STAGE;
#pragma unroll
        for (int kk = 0; kk < 4; kk++) {
            uint32_t bf[4][2];
#pragma unroll
            for (int np = 0; np < 2; np++)
                ldsm_x4(bf[np * 2][0], bf[np * 2][1], bf[np * 2 + 1][0], bf[np * 2 + 1][1],
                        spkb + SWZ128(bbyte[np] + kk * 32));
#pragma unroll
            for (int p = 0; p < 2; p++) {
                uint32_t af[2][4];
#pragma unroll
                for (int mt = 0; mt < 2; mt++)
                    ldsm_x4(af[mt][0], af[mt][1], af[mt][2], af[mt][3],
                            w2b + p * PB_W2TILE + SWZ128(abyte[mt] + kk * 32));
#pragma unroll
                for (int mt = 0; mt < 2; mt++)
#pragma unroll
                    for (int nt = 0; nt < 4; nt++)
                        mma16816_bf16(acc[mt][nt], af[mt], bf[nt]);
            }
        }

        if (kc + 1 < PB_NCH) {
#pragma unroll
            for (int i = 0; i < 2; i++) mcur[i] = mrow[i][(kc + 1) * 2];
        }
    }

#pragma unroll
    for (int mt = 0; mt < 2; mt++) {
#pragma unroll
        for (int nt = 0; nt < 4; nt++) {
            int o  = mt * 16 + (lane >> 2);
            int n  = wid * 32 + nt * 8 + (lane & 3) * 2;
            size_t gm = (size_t)(m0 + n);
            g_d2[gm * 32 + o]           = acc[mt][nt][0];
            g_d2[(gm + 1) * 32 + o]     = acc[mt][nt][1];
            g_d2[gm * 32 + o + 8]       = acc[mt][nt][2];
            g_d2[(gm + 1) * 32 + o + 8] = acc[mt][nt][3];
        }
    }
}

// ---------------------------------------------------------------------------
// Kernel 2c: readout EMA + softmax accumulate, SHFL-FREE (R13-proven).
// ---------------------------------------------------------------------------
__global__ __launch_bounds__(256) void readout_kernel(
    const float* __restrict__ tau2,
    const float* __restrict__ b2,
    float* __restrict__ out)
{
    __shared__ float e_buf[8][32][21];
    __shared__ float rs_buf[8][32];

    const int warp = threadIdx.x >> 5;
    const int lane = threadIdx.x & 31;
    const int b = blockIdx.x * 8 + warp;

    float a2 = 0.0f, oma2 = 0.0f, bb = 0.0f, mem2 = 0.0f, accv = 0.0f;
    if (lane < O_) {
        a2 = 1.0f / (1.0f + expf(-tau2[lane]));
        oma2 = 1.0f - a2;
        bb = b2[lane];
    }

    const float* dp = g_d2 + (size_t)b * T_ * 32;
    float pre[4];
#pragma unroll
    for (int i = 0; i < 4; i++)
        pre[i] = dp[(size_t)i * 32 + lane];

    int t = 0;
    for (int c = 0; c < 8; c++) {
        const int len = (c == 7) ? (T_ - 7 * 32) : 32;

        for (int tt = 0; tt < len; tt++, t++) {
            float v = pre[t & 3];
            if (t + 4 < T_) pre[t & 3] = dp[(size_t)(t + 4) * 32 + lane];
            if (lane < O_) {
                mem2 = mem2 * a2 + oma2 * (v + bb);
                e_buf[warp][tt][lane] = expf(mem2);
            }
        }
        __syncwarp();

        if (lane < len) {
            float s0 = 0.0f, s1 = 0.0f;
#pragma unroll
            for (int o = 0; o < O_; o += 2) {
                s0 += e_buf[warp][lane][o];
                s1 += e_buf[warp][lane][o + 1];
            }
            rs_buf[warp][lane] = 1.0f / (s0 + s1);
        }
        __syncwarp();

        if (lane < O_) {
            const int tbase = c * 32;
            for (int tt = 0; tt < len; tt++) {
                if (tbase + tt > 10)
                    accv += e_buf[warp][tt][lane] * rs_buf[warp][tt];
            }
        }
        __syncwarp();
    }

    if (lane < O_) out[b * O_ + lane] = accv;
}

// ---------------------------------------------------------------------------
extern "C" void kernel_launch(void* const* d_in, const int* in_sizes, int n_in,
                              void* d_out, int out_size)
{
    const float* input = (const float*)d_in[0];  // [B,T,D]
    const float* W1    = (const float*)d_in[1];  // [H,D]
    const float* b1    = (const float*)d_in[2];  // [H]
    const float* tau1  = (const float*)d_in[3];  // [H]
    const float* W2    = (const float*)d_in[4];  // [O,H]
    const float* b2    = (const float*)d_in[5];  // [O]
    const float* tau2  = (const float*)d_in[6];  // [O]
    float* out = (float*)d_out;                  // [B,O]

    cudaFuncSetAttribute(gemm_hmma_kernel,
                         cudaFuncAttributeMaxDynamicSharedMemorySize, SMEM_TOTAL);
    cudaFuncSetAttribute(d2_gemm_kernel,
                         cudaFuncAttributeMaxDynamicSharedMemorySize, PB_SMEM);

    __half *ah, *al, *wh, *wl;
    float *d1p;
    cudaGetSymbolAddress((void**)&ah,  g_Ah);
    cudaGetSymbolAddress((void**)&al,  g_Al);
    cudaGetSymbolAddress((void**)&wh,  g_Wh);
    cudaGetSymbolAddress((void**)&wl,  g_Wl);
    cudaGetSymbolAddress((void**)&d1p, g_d1);

    {
        long long total = (long long)(M_ + H_) * (KP_ / 8) + 32LL * PB_K;
        int blocks = (int)((total + 255) / 256);
        prep_kernel<<<blocks, 256>>>(input, W1, W2, ah, al, wh, wl);
    }

    dim3 ggrid(H_ / BN, M_ / BM);  // (16, 500) = 8000 CTAs
    gemm_hmma_kernel<<<ggrid, 256, SMEM_TOTAL>>>(b1);

    lif1_kernel<<<2 * B_, 128>>>(d1p, tau1);
    d2_gemm_kernel<<<M_ / PB_ROWS, 256, PB_SMEM>>>();   // 250 CTAs
    readout_kernel<<<B_ / 8, 256>>>(tau2, b2, out);
}

// round 15
// speedup vs baseline: 1.2287x; 1.0831x over previous
#include <cuda_runtime.h>
#include <cuda_fp16.h>
#include <cuda_bf16.h>
#include <math_constants.h>
#include <cstdint>

// ---------------- shapes ----------------
#define B_  256
#define T_  250
#define D_  700
#define H_  1024
#define O_  20
#define M_  (B_ * T_)   // 64000
#define KP_ 704         // K padded to multiple of 64

// ---------------- main GEMM tiling (FROZEN) ----------------
#define BM 128
#define BN 64
#define BK 64
#define NCHUNK (KP_ / BK)              // 11
#define A_TILE_B (BM * BK * 2)         // 16384
#define W_TILE_B (BN * BK * 2)         // 8192
#define STAGE_B (2 * A_TILE_B + 2 * W_TILE_B)  // 49152
#define NSTAGE 2
#define SMEM_TOTAL (NSTAGE * STAGE_B)  // 98304 -> 2 CTAs/SM

#define A_SCALE 2048.0f
#define W_SCALE 64.0f
#define INV_SCALE (1.0f / (A_SCALE * W_SCALE))   // 2^-17, exact

// ---------------- phase-B (d2+readout fused) tiling ----------------
#define PB_ROWS 256                        // padded t rows (250 valid)
#define PB_K    1024
#define PB_BK   64
#define PB_NCH  (PB_K / PB_BK)             // 16
#define PB_SPKBUF  (PB_ROWS * PB_BK * 2)   // 32768 per buffer
#define PB_W2TILE  (32 * PB_BK * 2)        // 4096 per split
#define PB_W2STAGE (2 * PB_W2TILE)         // 8192
#define PB_W2RING  4
#define PB_LUT_OFF (2 * PB_SPKBUF + PB_W2RING * PB_W2STAGE)  // 98304
#define PB_SMEM (PB_LUT_OFF + 4096)        // 102400

// ---------------- scratch (static device globals; no allocation) ----------------
__device__ float g_d1[(size_t)M_ * H_];
__device__ __half g_Ah[(size_t)M_ * KP_];
__device__ __half g_Al[(size_t)M_ * KP_];
__device__ __half g_Wh[(size_t)H_ * KP_];
__device__ __half g_Wl[(size_t)H_ * KP_];
__device__ uint32_t g_msk[(size_t)M_ * 32];            // spike bitmasks
__device__ __nv_bfloat16 g_W2s[2][32 * PB_K];          // W2 hi/lo bf16 splits (bit-permuted)

// ---------------- family-safe PTX helpers ----------------
__device__ __forceinline__ uint32_t smem_to_u32(const void* smem_ptr) {
    uint32_t addr;
    asm("{ .reg .u64 tmp; cvta.to.shared.u64 tmp, %1; cvt.u32.u64 %0, tmp; }"
        : "=r"(addr) : "l"(smem_ptr));
    return addr;
}
#define CP_ASYNC16(dst_u32, src_ptr) \
    asm volatile("cp.async.cg.shared.global [%0], [%1], 16;" \
        :: "r"(dst_u32), "l"(src_ptr))
#define CP_COMMIT() asm volatile("cp.async.commit_group;" ::: "memory")
#define CP_WAIT1()  asm volatile("cp.async.wait_group 1;" ::: "memory")

__device__ __forceinline__ void ldsm_x4(uint32_t& r0, uint32_t& r1,
                                        uint32_t& r2, uint32_t& r3, uint32_t addr) {
    asm volatile("ldmatrix.sync.aligned.m8n8.x4.shared.b16 {%0,%1,%2,%3}, [%4];"
        : "=r"(r0), "=r"(r1), "=r"(r2), "=r"(r3) : "r"(addr));
}
__device__ __forceinline__ void mma16816_f16(float* c, const uint32_t* a, const uint32_t* b) {
    asm volatile(
        "mma.sync.aligned.m16n8k16.row.col.f32.f16.f16.f32 "
        "{%0,%1,%2,%3}, {%4,%5,%6,%7}, {%8,%9}, {%0,%1,%2,%3};"
        : "+f"(c[0]), "+f"(c[1]), "+f"(c[2]), "+f"(c[3])
        : "r"(a[0]), "r"(a[1]), "r"(a[2]), "r"(a[3]), "r"(b[0]), "r"(b[1]));
}
__device__ __forceinline__ void mma16816_bf16(float* c, const uint32_t* a, const uint32_t* b) {
    asm volatile(
        "mma.sync.aligned.m16n8k16.row.col.f32.bf16.bf16.f32 "
        "{%0,%1,%2,%3}, {%4,%5,%6,%7}, {%8,%9}, {%0,%1,%2,%3};"
        : "+f"(c[0]), "+f"(c[1]), "+f"(c[2]), "+f"(c[3])
        : "r"(a[0]), "r"(a[1]), "r"(a[2]), "r"(a[3]), "r"(b[0]), "r"(b[1]));
}
#define SWZ128(o) ((o) ^ (((o) >> 3) & 0x70))

// expand 2 spike bits into packed bf16x2 (1.0f / 0.0f halves)
__device__ __forceinline__ uint32_t expand2(uint32_t b) {
    return ((b & 1u) * 0x3F80u) | ((b >> 1) * 0x3F800000u);
}

// ---------------------------------------------------------------------------
// Kernel 0: fused prep (FROZEN from R13).
// ---------------------------------------------------------------------------
__global__ void prep_kernel(const float* __restrict__ input,
                            const float* __restrict__ W1,
                            const float* __restrict__ W2,
                            __half* __restrict__ ah, __half* __restrict__ al,
                            __half* __restrict__ wh, __half* __restrict__ wl)
{
    const int GPR = KP_ / 8;  // 88
    const long long total1 = (long long)(M_ + H_) * GPR;
    long long idx = (long long)blockIdx.x * blockDim.x + threadIdx.x;

    if (idx < total1) {
        int mrow = (int)(idx / GPR);
        int g    = (int)(idx % GPR);
        const float* src;
        float scale;
        __half *o0, *o1;
        int row;
        if (mrow < M_) { src = input; scale = A_SCALE; o0 = ah; o1 = al; row = mrow; }
        else           { src = W1;    scale = W_SCALE; o0 = wh; o1 = wl; row = mrow - M_; }

        const float* sp = src + (size_t)row * D_ + g * 8;
        float4 f0 = __ldcs((const float4*)sp);
        float4 f1 = (g < GPR - 1) ? __ldcs((const float4*)(sp + 4))
                                  : make_float4(0.f, 0.f, 0.f, 0.f);
        float a[8] = {f0.x * scale, f0.y * scale, f0.z * scale, f0.w * scale,
                      f1.x * scale, f1.y * scale, f1.z * scale, f1.w * scale};
        unsigned short h0[8], h1[8];
#pragma unroll
        for (int i = 0; i < 8; i++) {
            __half hi = __float2half_rn(a[i]);
            __half lo = __float2half_rn(a[i] - __half2float(hi));
            h0[i] = __half_as_ushort(hi);
            h1[i] = __half_as_ushort(lo);
        }
        size_t off = (size_t)row * KP_ + g * 8;
        *(uint4*)(o0 + off) = make_uint4(
            (uint32_t)h0[1] << 16 | h0[0], (uint32_t)h0[3] << 16 | h0[2],
            (uint32_t)h0[5] << 16 | h0[4], (uint32_t)h0[7] << 16 | h0[6]);
        *(uint4*)(o1 + off) = make_uint4(
            (uint32_t)h1[1] << 16 | h1[0], (uint32_t)h1[3] << 16 | h1[2],
            (uint32_t)h1[5] << 16 | h1[4], (uint32_t)h1[7] << 16 | h1[6]);
    } else {
        long long j = idx - total1;
        if (j < 32 * PB_K) {
            int o = (int)(j / PB_K);
            int p = (int)(j % PB_K);
            int w = p >> 5, l = p & 31;
            int h = (w >> 2) * 128 + l * 4 + (w & 3);
            float v = (o < O_) ? W2[o * H_ + h] : 0.0f;
            __nv_bfloat16 hi = __float2bfloat16(v);
            __nv_bfloat16 lo = __float2bfloat16(v - __bfloat162float(hi));
            g_W2s[0][j] = hi;
            g_W2s[1][j] = lo;
        }
    }
}

// ---------------------------------------------------------------------------
// Kernel 1: HMMA fp16 GEMM (FROZEN, R7/R9 byte-for-byte).
// ---------------------------------------------------------------------------
__global__ __launch_bounds__(256, 2)
void gemm_hmma_kernel(const float* __restrict__ bias)
{
    extern __shared__ __align__(1024) char smem[];
    const uint32_t smem_base = smem_to_u32(smem);
    const int tid  = threadIdx.x;
    const int wid  = tid >> 5;
    const int lane = tid & 31;
    const int wm = wid >> 1;
    const int wn = wid & 1;
    const int bm = blockIdx.y * BM;
    const int bn = blockIdx.x * BN;

    uint32_t sdstA[4];
    size_t   goffA[4];
#pragma unroll
    for (int j = 0; j < 4; j++) {
        int c = tid + j * 256;
        int row = c >> 3, unit = c & 7;
        sdstA[j] = SWZ128(row * 128 + unit * 16);
        goffA[j] = (size_t)row * KP_ + unit * 8;
    }
    uint32_t sdstW[2];
    size_t   goffW[2];
#pragma unroll
    for (int j = 0; j < 2; j++) {
        int c = tid + j * 256;
        int row = c >> 3, unit = c & 7;
        sdstW[j] = SWZ128(row * 128 + unit * 16);
        goffW[j] = (size_t)row * KP_ + unit * 8;
    }
    const __half* Asrc[2] = { g_Ah + (size_t)bm * KP_, g_Al + (size_t)bm * KP_ };
    const __half* Wsrc[2] = { g_Wh + (size_t)bn * KP_, g_Wl + (size_t)bn * KP_ };

    const int q  = lane >> 3;
    const int rr = lane & 7;
    uint32_t abyte[2];
#pragma unroll
    for (int mt = 0; mt < 2; mt++) {
        int row = wm * 32 + mt * 16 + (q & 1) * 8 + rr;
        abyte[mt] = (uint32_t)(row * 128 + (q >> 1) * 16);
    }
    uint32_t bbyte[2];
#pragma unroll
    for (int np = 0; np < 2; np++) {
        int row = wn * 32 + np * 16 + (q >> 1) * 8 + rr;
        bbyte[np] = (uint32_t)(row * 128 + (q & 1) * 16);
    }

    float acc[2][4][4];
#pragma unroll
    for (int mt = 0; mt < 2; mt++)
#pragma unroll
        for (int nt = 0; nt < 4; nt++)
#pragma unroll
            for (int i = 0; i < 4; i++) acc[mt][nt][i] = 0.0f;

#define GEMM_LOAD_CHUNK(sb, k0) do { \
    _Pragma("unroll") \
    for (int s = 0; s < 2; s++) { \
        _Pragma("unroll") \
        for (int j = 0; j < 4; j++) \
            CP_ASYNC16((sb) + s * A_TILE_B + sdstA[j], Asrc[s] + goffA[j] + (k0)); \
        _Pragma("unroll") \
        for (int j = 0; j < 2; j++) \
            CP_ASYNC16((sb) + 2 * A_TILE_B + s * W_TILE_B + sdstW[j], \
                       Wsrc[s] + goffW[j] + (k0)); \
    } \
} while (0)

    GEMM_LOAD_CHUNK(smem_base, 0);
    CP_COMMIT();
    GEMM_LOAD_CHUNK(smem_base + STAGE_B, BK);
    CP_COMMIT();

    const int pa[3] = {0, 0, 1};
    const int pb[3] = {0, 1, 0};

    for (int k = 0; k < NCHUNK; k++) {
        CP_WAIT1();
        __syncthreads();

        const uint32_t stage = smem_base + (k & 1) * STAGE_B;
#pragma unroll
        for (int kk = 0; kk < 4; kk++) {
            uint32_t af[2][2][4];
            uint32_t bf[2][4][2];
#pragma unroll
            for (int s = 0; s < 2; s++) {
#pragma unroll
                for (int mt = 0; mt < 2; mt++)
                    ldsm_x4(af[s][mt][0], af[s][mt][1], af[s][mt][2], af[s][mt][3],
                            stage + s * A_TILE_B + SWZ128(abyte[mt] + kk * 32));
#pragma unroll
                for (int np = 0; np < 2; np++)
                    ldsm_x4(bf[s][np * 2][0], bf[s][np * 2][1],
                            bf[s][np * 2 + 1][0], bf[s][np * 2 + 1][1],
                            stage + 2 * A_TILE_B + s * W_TILE_B
                                  + SWZ128(bbyte[np] + kk * 32));
            }
#pragma unroll
            for (int p = 0; p < 3; p++)
#pragma unroll
                for (int mt = 0; mt < 2; mt++)
#pragma unroll
                    for (int nt = 0; nt < 4; nt++)
                        mma16816_f16(acc[mt][nt], af[pa[p]][mt], bf[pb[p]][nt]);
        }
        __syncthreads();

        if (k + NSTAGE < NCHUNK) {
            GEMM_LOAD_CHUNK(smem_base + (k & 1) * STAGE_B, (k + NSTAGE) * BK);
        }
        CP_COMMIT();
    }

    const int mrow0 = bm + wm * 32;
    const int ncol0 = bn + wn * 32;
    const int lr = lane >> 2;
    const int lc = (lane & 3) * 2;
#pragma unroll
    for (int mt = 0; mt < 2; mt++) {
#pragma unroll
        for (int nt = 0; nt < 4; nt++) {
            int r = mrow0 + mt * 16 + lr;
            int c = ncol0 + nt * 8 + lc;
            float bx = __ldg(bias + c), by = __ldg(bias + c + 1);
            float2 v0 = make_float2(acc[mt][nt][0] * INV_SCALE + bx,
                                    acc[mt][nt][1] * INV_SCALE + by);
            float2 v1 = make_float2(acc[mt][nt][2] * INV_SCALE + bx,
                                    acc[mt][nt][3] * INV_SCALE + by);
            *(float2*)(g_d1 + (size_t)r * H_ + c)       = v0;
            *(float2*)(g_d1 + (size_t)(r + 8) * H_ + c) = v1;
        }
    }
}

// ---------------------------------------------------------------------------
// Kernel 2a: LIF layer-1 chains -> spike BITMASKS (FROZEN from R14).
// ---------------------------------------------------------------------------
__global__ __launch_bounds__(128) void lif1_kernel(
    const float* __restrict__ d1,
    const float* __restrict__ tau1)
{
    const int b    = blockIdx.x >> 1;
    const int half = blockIdx.x & 1;
    const int tid  = threadIdx.x;
    const int wl   = tid >> 5;
    const int lane = tid & 31;
    const int h0   = half * 512 + tid * 4;

    float4 tv = *(const float4*)(tau1 + h0);
    float a1[4], om[4], mem[4], spk[4];
    a1[0] = 1.0f / (1.0f + expf(-tv.x));
    a1[1] = 1.0f / (1.0f + expf(-tv.y));
    a1[2] = 1.0f / (1.0f + expf(-tv.z));
    a1[3] = 1.0f / (1.0f + expf(-tv.w));
#pragma unroll
    for (int j = 0; j < 4; j++) { om[j] = 1.0f - a1[j]; mem[j] = 0.0f; spk[j] = 0.0f; }

    const float* dp = d1 + (size_t)b * T_ * H_ + h0;
    uint32_t* mp = g_msk + (size_t)b * T_ * 32 + (half * 4 + wl) * 4;

    float4 pre[8];
#pragma unroll
    for (int i = 0; i < 8; i++)
        pre[i] = __ldcs((const float4*)(dp + (size_t)i * H_));

#pragma unroll 8
    for (int t = 0; t < T_; t++) {
        float4 c = pre[t & 7];
        if (t + 8 < T_)
            pre[t & 7] = __ldcs((const float4*)(dp + (size_t)(t + 8) * H_));
        float cur[4] = {c.x, c.y, c.z, c.w};

#pragma unroll
        for (int j = 0; j < 4; j++) {
            mem[j] = mem[j] * a1[j] + om[j] * cur[j] - spk[j];
            spk[j] = (mem[j] > 1.0f) ? 1.0f : 0.0f;
        }
        uint32_t bits0 = __ballot_sync(0xffffffffu, mem[0] > 1.0f);
        uint32_t bits1 = __ballot_sync(0xffffffffu, mem[1] > 1.0f);
        uint32_t bits2 = __ballot_sync(0xffffffffu, mem[2] > 1.0f);
        uint32_t bits3 = __ballot_sync(0xffffffffu, mem[3] > 1.0f);
        if (lane < 4) {
            uint32_t w = (lane == 0) ? bits0 : (lane == 1) ? bits1
                       : (lane == 2) ? bits2 : bits3;
            mp[(size_t)t * 32 + lane] = w;
        }
    }
}

// ---------------------------------------------------------------------------
// Kernel 2b: FUSED d2 GEMM + readout. One CTA per sample (grid 256).
// Rows = t (0..249, padded to 256). Single barrier per K-chunk: expansion of
// chunk kc+1 overlaps MMA of chunk kc. Epilogue stores d2^T to smem; warp 0
// runs the 3-pass readout in place. No g_d2 gmem roundtrip.
// ---------------------------------------------------------------------------
__global__ __launch_bounds__(256, 2)
void d2_readout_kernel(const float* __restrict__ tau2,
                       const float* __restrict__ b2,
                       float* __restrict__ out)
{
    extern __shared__ __align__(1024) char smem[];
    const uint32_t smem_base = smem_to_u32(smem);
    uint4* lut = (uint4*)(smem + PB_LUT_OFF);
    const int tid  = threadIdx.x;
    const int wid  = tid >> 5;
    const int lane = tid & 31;
    const int b  = blockIdx.x;
    const int m0 = b * T_;

    // build LUT (256 entries, one per thread)
    {
        uint32_t v = (uint32_t)tid;
        uint4 u;
        u.x = expand2(v & 3u);
        u.y = expand2((v >> 2) & 3u);
        u.z = expand2((v >> 4) & 3u);
        u.w = expand2((v >> 6) & 3u);
        lut[tid] = u;
    }

    // expansion geometry (rows 250..255 duplicate row 249; results unused)
    uint32_t ebase[2];
    const uint32_t* mrow[2];
#pragma unroll
    for (int i = 0; i < 2; i++) {
        int idx = tid + i * 256;
        int r = idx >> 1, wq = idx & 1;
        int rg = (r < T_) ? r : (T_ - 1);
        ebase[i] = (uint32_t)(r * 128 + wq * 64);
        mrow[i]  = g_msk + (size_t)(m0 + rg) * 32 + wq;
    }

    // W2 cp.async geometry
    const int wrow = tid >> 3, wunit = tid & 7;
    const uint32_t w_sdst = SWZ128(wrow * 128 + wunit * 16);
    const size_t   w_goff = (size_t)wrow * PB_K + wunit * 8;
    const uint32_t w2smem = smem_base + 2 * PB_SPKBUF;

    // ldmatrix addresses
    const int q  = lane >> 3;
    const int rr = lane & 7;
    uint32_t abyte[2];
#pragma unroll
    for (int mt = 0; mt < 2; mt++) {
        int row = mt * 16 + (q & 1) * 8 + rr;
        abyte[mt] = (uint32_t)(row * 128 + (q >> 1) * 16);
    }
    uint32_t bbyte[2];
#pragma unroll
    for (int np = 0; np < 2; np++) {
        int row = wid * 32 + np * 16 + (q >> 1) * 8 + rr;
        bbyte[np] = (uint32_t)(row * 128 + (q & 1) * 16);
    }

    float acc[2][4][4];
#pragma unroll
    for (int mt = 0; mt < 2; mt++)
#pragma unroll
        for (int nt = 0; nt < 4; nt++)
#pragma unroll
            for (int i = 0; i < 4; i++) acc[mt][nt][i] = 0.0f;

    // prologue: W2 chunks 0,1; LUT barrier; expand chunk 0; per-thread wait ch0
#pragma unroll
    for (int pk = 0; pk < 2; pk++) {
#pragma unroll
        for (int p = 0; p < 2; p++)
            CP_ASYNC16(w2smem + pk * PB_W2STAGE + p * PB_W2TILE + w_sdst,
                       &g_W2s[p][0] + w_goff + pk * PB_BK);
        CP_COMMIT();
    }
    uint32_t mcur[2];
#pragma unroll
    for (int i = 0; i < 2; i++) mcur[i] = mrow[i][0];
    __syncthreads();   // LUT visible
    {
        char* sb = smem;   // buf0
#pragma unroll
        for (int i = 0; i < 2; i++) {
            uint32_t W = mcur[i];
#pragma unroll
            for (int g = 0; g < 4; g++)
                *(uint4*)(sb + SWZ128(ebase[i] + g * 16)) = lut[(W >> (g * 8)) & 0xFFu];
        }
    }
    CP_WAIT1();        // own W2 chunk-0 copies complete

    for (int kc = 0; kc < PB_NCH; kc++) {
        __syncthreads();   // expansion(kc)+W2(kc) visible; buf[(kc+1)&1] free

        // prefetch W2 chunk kc+2
        if (kc + 2 < PB_NCH) {
#pragma unroll
            for (int p = 0; p < 2; p++)
                CP_ASYNC16(w2smem + ((kc + 2) & 3) * PB_W2STAGE + p * PB_W2TILE + w_sdst,
                           &g_W2s[p][0] + w_goff + (kc + 2) * PB_BK);
        }
        CP_COMMIT();

        // expand chunk kc+1 (overlaps MMA of kc below)
        if (kc + 1 < PB_NCH) {
#pragma unroll
            for (int i = 0; i < 2; i++) mcur[i] = mrow[i][(kc + 1) * 2];
            char* sb = smem + ((kc + 1) & 1) * PB_SPKBUF;
#pragma unroll
            for (int i = 0; i < 2; i++) {
                uint32_t W = mcur[i];
#pragma unroll
                for (int g = 0; g < 4; g++)
                    *(uint4*)(sb + SWZ128(ebase[i] + g * 16)) = lut[(W >> (g * 8)) & 0xFFu];
            }
        }
        CP_WAIT1();        // own W2 chunk kc+1 copies complete

        // MMA chunk kc
        const uint32_t spkb = smem_base + (kc & 1) * PB_SPKBUF;
        const uint32_t w2b  = w2smem + (kc & 3) * PB_W2STAGE;
#pragma unroll
        for (int kk = 0; kk < 4; kk++) {
            uint32_t bf[4][2];
#pragma unroll
            for (int np = 0; np < 2; np++)
                ldsm_x4(bf[np * 2][0], bf[np * 2][1], bf[np * 2 + 1][0], bf[np * 2 + 1][1],
                        spkb + SWZ128(bbyte[np] + kk * 32));
#pragma unroll
            for (int p = 0; p < 2; p++) {
                uint32_t af[2][4];
#pragma unroll
                for (int mt = 0; mt < 2; mt++)
                    ldsm_x4(af[mt][0], af[mt][1], af[mt][2], af[mt][3],
                            w2b + p * PB_W2TILE + SWZ128(abyte[mt] + kk * 32));
#pragma unroll
                for (int mt = 0; mt < 2; mt++)
#pragma unroll
                    for (int nt = 0; nt < 4; nt++)
                        mma16816_bf16(acc[mt][nt], af[mt], bf[nt]);
            }
        }
    }

    // ---- epilogue: d2^T fragments -> smem (reuse spk buffers) ----
    __syncthreads();   // all MMAs done before overwriting spike buffers
    float* d2s = (float*)smem;               // [256][33] floats = 33792 B
    float* rs  = (float*)(smem + 34048);     // 32 floats
#pragma unroll
    for (int mt = 0; mt < 2; mt++) {
#pragma unroll
        for (int nt = 0; nt < 4; nt++) {
            int o = mt * 16 + (lane >> 2);
            int t = wid * 32 + nt * 8 + (lane & 3) * 2;
            d2s[t * 33 + o]           = acc[mt][nt][0];
            d2s[(t + 1) * 33 + o]     = acc[mt][nt][1];
            d2s[t * 33 + o + 8]       = acc[mt][nt][2];
            d2s[(t + 1) * 33 + o + 8] = acc[mt][nt][3];
        }
    }
    __syncthreads();

    // ---- readout (warp 0 only), R13 3-pass arithmetic in place ----
    if (wid == 0) {
        float a2 = 0.0f, oma2 = 0.0f, bb = 0.0f, mem2 = 0.0f, accv = 0.0f;
        if (lane < O_) {
            a2 = 1.0f / (1.0f + expf(-tau2[lane]));
            oma2 = 1.0f - a2;
            bb = b2[lane];
        }
        for (int c = 0; c < 8; c++) {
            const int len = (c == 7) ? (T_ - 7 * 32) : 32;   // 26 last
            if (lane < O_) {
                for (int tt = 0; tt < len; tt++) {
                    int t = c * 32 + tt;
                    float v = d2s[t * 33 + lane];
                    mem2 = mem2 * a2 + oma2 * (v + bb);
                    d2s[t * 33 + lane] = expf(mem2);
                }
            }
            __syncwarp();
            if (lane < len) {
                float s0 = 0.0f, s1 = 0.0f;
#pragma unroll
                for (int o = 0; o < O_; o += 2) {
                    s0 += d2s[(c * 32 + lane) * 33 + o];
                    s1 += d2s[(c * 32 + lane) * 33 + o + 1];
                }
                rs[lane] = 1.0f / (s0 + s1);
            }
            __syncwarp();
            if (lane < O_) {
                const int tbase = c * 32;
                for (int tt = 0; tt < len; tt++) {
                    if (tbase + tt > 10)
                        accv += d2s[(tbase + tt) * 33 + lane] * rs[tt];
                }
            }
            __syncwarp();
        }
        if (lane < O_) out[b * O_ + lane] = accv;
    }
}

// ---------------------------------------------------------------------------
extern "C" void kernel_launch(void* const* d_in, const int* in_sizes, int n_in,
                              void* d_out, int out_size)
{
    const float* input = (const float*)d_in[0];  // [B,T,D]
    const float* W1    = (const float*)d_in[1];  // [H,D]
    const float* b1    = (const float*)d_in[2];  // [H]
    const float* tau1  = (const float*)d_in[3];  // [H]
    const float* W2    = (const float*)d_in[4];  // [O,H]
    const float* b2    = (const float*)d_in[5];  // [O]
    const float* tau2  = (const float*)d_in[6];  // [O]
    float* out = (float*)d_out;                  // [B,O]

    cudaFuncSetAttribute(gemm_hmma_kernel,
                         cudaFuncAttributeMaxDynamicSharedMemorySize, SMEM_TOTAL);
    cudaFuncSetAttribute(d2_readout_kernel,
                         cudaFuncAttributeMaxDynamicSharedMemorySize, PB_SMEM);

    __half *ah, *al, *wh, *wl;
    float *d1p;
    cudaGetSymbolAddress((void**)&ah,  g_Ah);
    cudaGetSymbolAddress((void**)&al,  g_Al);
    cudaGetSymbolAddress((void**)&wh,  g_Wh);
    cudaGetSymbolAddress((void**)&wl,  g_Wl);
    cudaGetSymbolAddress((void**)&d1p, g_d1);

    {
        long long total = (long long)(M_ + H_) * (KP_ / 8) + 32LL * PB_K;
        int blocks = (int)((total + 255) / 256);
        prep_kernel<<<blocks, 256>>>(input, W1, W2, ah, al, wh, wl);
    }

    dim3 ggrid(H_ / BN, M_ / BM);  // (16, 500) = 8000 CTAs
    gemm_hmma_kernel<<<ggrid, 256, SMEM_TOTAL>>>(b1);

    lif1_kernel<<<2 * B_, 128>>>(d1p, tau1);
    d2_readout_kernel<<<B_, 256, PB_SMEM>>>(tau2, b2, out);
}